// round 9
// baseline (speedup 1.0000x reference)
#include <cuda_runtime.h>
#include <cuda_bf16.h>
#include <cuda_fp16.h>
#include <math_constants.h>
#include <cstdint>

// Problem constants
#define BATCH 4
#define SLEN  32768
#define C1    128
#define C2    256
#define HID   512
#define L1LEN 16384
#define L2LEN 8192
#define L3LEN 4096
#define VOCAB 2048
#define KCB   4
#define NTOK  (BATCH * KCB * L3LEN)      // 65536

// ------------------- device scratch (device-code references ONLY) -------------------
__device__ __align__(16) float g_conv1[BATCH * C1 * L1LEN];
__device__ __align__(16) float g_conv2[BATCH * C2 * L2LEN];
__device__ __align__(16) float g_feats[BATCH * L3LEN * HID];       // fp32 exact
__device__ __align__(16) float g_w2t[C2 * C1 * 7];                 // [(ci*7+t)][co]
__device__ __align__(16) float g_w3t[HID * C2 * 7];
__device__ __align__(16) __nv_bfloat16 g_fhi[BATCH * L3LEN * HID];
__device__ __align__(16) __nv_bfloat16 g_chi[KCB * VOCAB * HID];
__device__ __align__(16) __half g_cross[(size_t)NTOK * VOCAB];     // 256MB approx cross
__device__ float g_c2[KCB * VOCAB];
__device__ float g_cbmax[KCB];
__device__ int   g_tokens[NTOK];

// ==================== weight transpose: w[co][ci][7] -> wt[(ci*7+t)][co] ====================
template <int CI, int CO, int STAGE>
__global__ void wtrans_kernel(const float* __restrict__ w) {
    float* wt = (STAGE == 2) ? g_w2t : g_w3t;
    int i = blockIdx.x * 256 + threadIdx.x;
    if (i >= CI * CO * 7) return;
    int co = i % CO;
    int row = i / CO;                 // ci*7 + t
    int ci = row / 7, t = row % 7;
    wt[i] = w[((size_t)co * CI + ci) * 7 + t];
}

// ==================== conv1: Cin=1, tile 64 l x 128 c ====================
__global__ __launch_bounds__(256) void conv1_fast_kernel(const float* __restrict__ x,
                                                         const float* __restrict__ w,
                                                         const float* __restrict__ bias) {
    __shared__ float a_s[136];
    int tid = threadIdx.x;
    int lane = tid & 31, lg = tid >> 5;
    int l0 = blockIdx.x * 64;
    int b = blockIdx.y;

    for (int p = tid; p < 133; p += 256) {
        int pg = 2 * l0 - 3 + p;
        a_s[p] = (pg >= 0 && pg < SLEN) ? x[(size_t)b * SLEN + pg] : 0.f;
    }
    __syncthreads();

    float wr[4][7], bv[4];
#pragma unroll
    for (int c = 0; c < 4; c++) {
        int ch = lane + 32 * c;
        bv[c] = bias[ch];
#pragma unroll
        for (int t = 0; t < 7; t++) wr[c][t] = w[ch * 7 + t];
    }

    float xv[21];
#pragma unroll
    for (int p = 0; p < 21; p++) xv[p] = a_s[16 * lg + p];

    float acc[4][8];
#pragma unroll
    for (int c = 0; c < 4; c++)
#pragma unroll
        for (int j = 0; j < 8; j++) acc[c][j] = bv[c];
#pragma unroll
    for (int t = 0; t < 7; t++) {
#pragma unroll
        for (int j = 0; j < 8; j++) {
            float xx = xv[2 * j + t];
#pragma unroll
            for (int c = 0; c < 4; c++)
                acc[c][j] = fmaf(wr[c][t], xx, acc[c][j]);
        }
    }
#pragma unroll
    for (int c = 0; c < 4; c++) {
        int ch = lane + 32 * c;
#pragma unroll
        for (int j = 0; j < 8; j++) {
            int l = l0 + lg * 8 + j;
            g_conv1[((size_t)b * C1 + ch) * L1LEN + l] = fmaxf(acc[c][j], 0.f);
        }
    }
}

// ==================== conv2/3: tile 64 l x 128 co, thread 4co x 8l ====================
template <int CI, int CO, int LOUT, bool RELU, bool TRANS_OUT, int STAGE>
__global__ __launch_bounds__(256) void conv_fast_kernel(const float* __restrict__ bias) {
    const float* in  = (STAGE == 2) ? g_conv1 : g_conv2;
    const float* wT  = (STAGE == 2) ? g_w2t : g_w3t;
    float*       out = (STAGE == 2) ? g_conv2 : g_feats;

    const int LIN = 2 * LOUT;
    __shared__ float in_s[8][136];
    __shared__ float w_s[56 * 128];

    int tid = threadIdx.x;
    int lane = tid & 31, lg = tid >> 5;
    int l0  = blockIdx.x * 64;
    int co0 = blockIdx.y * 128;
    int b   = blockIdx.z;

    float acc[4][8];
#pragma unroll
    for (int c = 0; c < 4; c++)
#pragma unroll
        for (int j = 0; j < 8; j++) acc[c][j] = 0.f;

    for (int ci0 = 0; ci0 < CI; ci0 += 8) {
        __syncthreads();
        for (int i = tid; i < 8 * 136; i += 256) {
            int ci = i / 136, p = i % 136;
            int pg = 2 * l0 - 3 + p;
            float v = 0.f;
            if (p < 133 && pg >= 0 && pg < LIN)
                v = in[((size_t)b * CI + ci0 + ci) * LIN + pg];
            in_s[ci][p] = v;
        }
        for (int i = tid; i < 56 * 128; i += 256) {
            int row = i >> 7, c = i & 127;
            w_s[i] = wT[(size_t)(ci0 * 7 + row) * CO + co0 + c];
        }
        __syncthreads();

#pragma unroll
        for (int ci = 0; ci < 8; ci++) {
            float xv[21];
#pragma unroll
            for (int p = 0; p < 21; p++) xv[p] = in_s[ci][16 * lg + p];
#pragma unroll
            for (int t = 0; t < 7; t++) {
                const float* wrow = &w_s[(ci * 7 + t) * 128];
                float w0 = wrow[lane];
                float w1 = wrow[lane + 32];
                float w2 = wrow[lane + 64];
                float w3 = wrow[lane + 96];
#pragma unroll
                for (int j = 0; j < 8; j++) {
                    float xx = xv[2 * j + t];
                    acc[0][j] = fmaf(w0, xx, acc[0][j]);
                    acc[1][j] = fmaf(w1, xx, acc[1][j]);
                    acc[2][j] = fmaf(w2, xx, acc[2][j]);
                    acc[3][j] = fmaf(w3, xx, acc[3][j]);
                }
            }
        }
    }

#pragma unroll
    for (int c = 0; c < 4; c++) {
        int co = co0 + lane + 32 * c;
        float bv = bias[co];
#pragma unroll
        for (int j = 0; j < 8; j++) {
            float r = acc[c][j] + bv;
            if (RELU) r = fmaxf(r, 0.f);
            int l = l0 + lg * 8 + j;
            if (TRANS_OUT)
                out[((size_t)b * LOUT + l) * CO + co] = r;
            else
                out[((size_t)b * CO + co) * LOUT + l] = r;
        }
    }
}

// ==================== bf16 hi conversions ====================
__global__ void split_feats_kernel() {
    int i = blockIdx.x * blockDim.x + threadIdx.x;
    if (i >= BATCH * L3LEN * HID) return;
    g_fhi[i] = __float2bfloat16_rn(g_feats[i]);
}
__global__ void split_cb_kernel(const float* __restrict__ cb) {
    int i = blockIdx.x * blockDim.x + threadIdx.x;
    if (i >= KCB * VOCAB * HID) return;
    g_chi[i] = __float2bfloat16_rn(cb[i]);
}

// ==================== c2 + per-codebook max norm ====================
__global__ void c2_kernel(const float* __restrict__ cb) {
    int row = blockIdx.x * 8 + (threadIdx.x >> 5);
    int lane = threadIdx.x & 31;
    const float* p = cb + (size_t)row * HID;
    float s = 0.f;
#pragma unroll 4
    for (int h = lane; h < HID; h += 32) {
        float v = p[h];
        s = fmaf(v, v, s);
    }
#pragma unroll
    for (int off = 16; off; off >>= 1)
        s += __shfl_xor_sync(0xffffffffu, s, off);
    if (lane == 0) g_c2[row] = s;
}

__global__ void cbmax_kernel() {
    __shared__ float red[256];
    int k = blockIdx.x;
    float m = 0.f;
    for (int v = threadIdx.x; v < VOCAB; v += 256)
        m = fmaxf(m, g_c2[k * VOCAB + v]);
    red[threadIdx.x] = m;
    __syncthreads();
    for (int s = 128; s; s >>= 1) {
        if (threadIdx.x < s) red[threadIdx.x] = fmaxf(red[threadIdx.x], red[threadIdx.x + s]);
        __syncthreads();
    }
    if (threadIdx.x == 0) g_cbmax[k] = sqrtf(red[0]);
}

// ==================== stage 1: pure bf16 hi GEMM -> fp16 cross ====================
#define ST_A 0
#define ST_B 18432
#define ST_STRIDE 55296        // A(128x144) + B(256x144)
#define ST_TOTAL 110592

__device__ __forceinline__ uint32_t smem_u32(const void* p) {
    uint32_t a;
    asm("{ .reg .u64 t; cvta.to.shared.u64 t, %1; cvt.u32.u64 %0, t; }" : "=r"(a) : "l"(p));
    return a;
}
__device__ __forceinline__ void cp_async16(uint32_t s, const void* g) {
    asm volatile("cp.async.cg.shared.global [%0], [%1], 16;" :: "r"(s), "l"(g) : "memory");
}
__device__ __forceinline__ void mma_bf16(float* c, const uint32_t* a, const uint32_t* b0, const uint32_t* b1) {
    asm volatile(
        "mma.sync.aligned.m16n8k16.row.col.f32.bf16.bf16.f32 "
        "{%0,%1,%2,%3}, {%4,%5,%6,%7}, {%8,%9}, {%0,%1,%2,%3};"
        : "+f"(c[0]), "+f"(c[1]), "+f"(c[2]), "+f"(c[3])
        : "r"(a[0]), "r"(a[1]), "r"(a[2]), "r"(a[3]), "r"(*b0), "r"(*b1));
}
__device__ __forceinline__ void ldsm_x4(uint32_t* r, uint32_t addr) {
    asm volatile("ldmatrix.sync.aligned.m8n8.x4.shared.b16 {%0,%1,%2,%3}, [%4];"
                 : "=r"(r[0]), "=r"(r[1]), "=r"(r[2]), "=r"(r[3]) : "r"(addr));
}

__global__ __launch_bounds__(256, 1) void gemm_hi_kernel() {
    extern __shared__ char smem[];
    uint32_t sbase = smem_u32(smem);

    const int tid = threadIdx.x;
    const int wid = tid >> 5, lane = tid & 31;
    const int wm = wid >> 2, wn = wid & 3;
    const int g = lane >> 2, t = lane & 3;
    const int lt = blockIdx.x;
    const int vt = blockIdx.y;
    const int bk = blockIdx.z;
    const int b = bk >> 2, k = bk & 3;

    const __nv_bfloat16* A  = g_fhi + ((size_t)b * L3LEN + lt * 128) * HID;
    const __nv_bfloat16* Bm = g_chi + ((size_t)k * VOCAB + vt * 256) * HID;

    auto load_chunk = [&](int kc, int s) {
        uint32_t st = sbase + s * ST_STRIDE;
#pragma unroll
        for (int j = 0; j < 12; j++) {
            int idx = tid + j * 256;
            if (idx < 1024) {
                int r = idx >> 3, q = idx & 7;
                cp_async16(st + ST_A + r * 144 + q * 16,
                           A + (size_t)r * HID + kc * 64 + q * 8);
            } else {
                int i2 = idx - 1024;
                int r = i2 >> 3, q = i2 & 7;
                cp_async16(st + ST_B + r * 144 + q * 16,
                           Bm + (size_t)r * HID + kc * 64 + q * 8);
            }
        }
        asm volatile("cp.async.commit_group;" ::: "memory");
    };

    // ldmatrix per-lane base addresses (row part), per stage buffer
    // lane l -> sub = l>>3: {rows +0 lo16, rows +8 lo16, rows +0 hi16, rows +8 hi16}
    int lrow = (lane & 7) + ((lane >> 3) & 1) * 8;
    int lcol = (lane >> 4) * 16;
    uint32_t a_ad[2][4], b_ad[2][4];
#pragma unroll
    for (int s = 0; s < 2; s++) {
#pragma unroll
        for (int mi = 0; mi < 4; mi++)
            a_ad[s][mi] = sbase + s * ST_STRIDE + ST_A +
                          (wm * 64 + mi * 16 + lrow) * 144 + lcol;
#pragma unroll
        for (int j = 0; j < 4; j++)
            b_ad[s][j] = sbase + s * ST_STRIDE + ST_B +
                         (wn * 64 + j * 16 + lrow) * 144 + lcol;
    }

    float acc[4][8][4];
#pragma unroll
    for (int mi = 0; mi < 4; mi++)
#pragma unroll
        for (int ni = 0; ni < 8; ni++)
#pragma unroll
            for (int j = 0; j < 4; j++) acc[mi][ni][j] = 0.f;

    load_chunk(0, 0);
    for (int kc = 0; kc < 8; kc++) {
        if (kc < 7) {
            load_chunk(kc + 1, (kc + 1) & 1);
            asm volatile("cp.async.wait_group 1;" ::: "memory");
        } else {
            asm volatile("cp.async.wait_group 0;" ::: "memory");
        }
        __syncthreads();
        int st = kc & 1;
#pragma unroll
        for (int ks = 0; ks < 4; ks++) {
            uint32_t af[4][4], bfv[4][4];
#pragma unroll
            for (int mi = 0; mi < 4; mi++) ldsm_x4(af[mi], a_ad[st][mi] + ks * 32);
#pragma unroll
            for (int j = 0; j < 4; j++)  ldsm_x4(bfv[j], b_ad[st][j] + ks * 32);
#pragma unroll
            for (int j = 0; j < 4; j++) {
#pragma unroll
                for (int mi = 0; mi < 4; mi++) {
                    mma_bf16(acc[mi][2 * j],     af[mi], &bfv[j][0], &bfv[j][2]);
                    mma_bf16(acc[mi][2 * j + 1], af[mi], &bfv[j][1], &bfv[j][3]);
                }
            }
        }
        __syncthreads();
    }

#pragma unroll
    for (int mi = 0; mi < 4; mi++) {
        int row = lt * 128 + wm * 64 + mi * 16 + g;
        size_t code = (size_t)(b * KCB + k) * L3LEN + row;
        __half* out0 = g_cross + code * VOCAB;
        __half* out1 = g_cross + (code + 8) * VOCAB;
#pragma unroll
        for (int ni = 0; ni < 8; ni++) {
            int col = vt * 256 + wn * 64 + ni * 8 + 2 * t;
            *(__half2*)(out0 + col) = __floats2half2_rn(acc[mi][ni][0], acc[mi][ni][1]);
            *(__half2*)(out1 + col) = __floats2half2_rn(acc[mi][ni][2], acc[mi][ni][3]);
        }
    }
}

// ==================== stage 2: per-token select + bounded exact rescore ====================
__device__ __forceinline__ void upd_min(float& m, float& m2, int& idx, float d, int v) {
    if (d < m)       { m2 = m; m = d; idx = v; }
    else if (d < m2) { m2 = d; }
}
__device__ __forceinline__ void merge_min(float& m, float& m2, int& idx,
                                          float om, float om2, int oidx) {
    if (om < m) { m2 = fminf(m, om2); m = om; idx = oidx; }
    else        { m2 = fminf(m2, om); }
}

__global__ __launch_bounds__(256) void select_kernel(const float* __restrict__ cb) {
    __shared__ float c2_s[VOCAB];
    int tid = threadIdx.x;
    int wid = tid >> 5, lane = tid & 31;
    int code0 = blockIdx.x * 8;
    int k = (code0 >> 12) & (KCB - 1);

    for (int i = tid; i < VOCAB; i += 256)
        c2_s[i] = g_c2[k * VOCAB + i];
    __syncthreads();

    int code = code0 + wid;
    int l = code & (L3LEN - 1);
    int b = code >> 14;
    const __half2* crow2 = (const __half2*)(g_cross + (size_t)code * VOCAB);

    float minv = CUDART_INF_F, min2 = CUDART_INF_F;
    int mini = 0;
#pragma unroll 4
    for (int i = 0; i < 32; i++) {
        __half2 h = crow2[i * 32 + lane];
        int v = i * 64 + lane * 2;
        float d0 = c2_s[v]     - 2.f * __low2float(h);
        float d1 = c2_s[v + 1] - 2.f * __high2float(h);
        upd_min(minv, min2, mini, d0, v);
        upd_min(minv, min2, mini, d1, v + 1);
    }
#pragma unroll
    for (int off = 16; off; off >>= 1) {
        float om  = __shfl_xor_sync(0xffffffffu, minv, off);
        float om2 = __shfl_xor_sync(0xffffffffu, min2, off);
        int   oi  = __shfl_xor_sync(0xffffffffu, mini, off);
        merge_min(minv, min2, mini, om, om2, oi);
    }

    const float* f = g_feats + ((size_t)b * L3LEN + l) * HID;
    float fr[16];
    float n2 = 0.f;
#pragma unroll
    for (int j = 0; j < 16; j++) {
        fr[j] = f[j * 32 + lane];
        n2 = fmaf(fr[j], fr[j], n2);
    }
#pragma unroll
    for (int off = 16; off; off >>= 1)
        n2 += __shfl_xor_sync(0xffffffffu, n2, off);

    float TH = 0.009f * sqrtf(n2) * g_cbmax[k] + 1.0f;

    if (min2 - minv > TH) {
        if (lane == 0) g_tokens[code] = mini;
        return;
    }

    float thr = minv + TH;
    float bestd = CUDART_INF_F;
    int besti = VOCAB;
    for (int i = 0; i < 32; i++) {
        __half2 h = crow2[i * 32 + lane];
        int v = i * 64 + lane * 2;
        float d0 = c2_s[v]     - 2.f * __low2float(h);
        float d1 = c2_s[v + 1] - 2.f * __high2float(h);
        unsigned m0 = __ballot_sync(0xffffffffu, d0 <= thr);
        unsigned m1 = __ballot_sync(0xffffffffu, d1 <= thr);
        while (m0 | m1) {
            int s0 = m0 ? (__ffs(m0) - 1) : 33;
            int s1 = m1 ? (__ffs(m1) - 1) : 33;
            int vc;
            if (s0 <= s1) { vc = i * 64 + s0 * 2;     m0 &= m0 - 1; }
            else          { vc = i * 64 + s1 * 2 + 1; m1 &= m1 - 1; }
            const float* c = cb + ((size_t)k * VOCAB + vc) * HID;
            float dot = 0.f;
#pragma unroll
            for (int j = 0; j < 16; j++)
                dot = fmaf(fr[j], c[j * 32 + lane], dot);
#pragma unroll
            for (int off = 16; off; off >>= 1)
                dot += __shfl_xor_sync(0xffffffffu, dot, off);
            float de = c2_s[vc] - 2.f * dot;
            if (de < bestd || (de == bestd && vc < besti)) { bestd = de; besti = vc; }
        }
    }
    if (lane == 0) g_tokens[code] = besti;
}

// ==================== outputs ====================
__global__ void emb_kernel(const float* __restrict__ embedding, float* __restrict__ out) {
    int bl = blockIdx.x;
    int b = bl >> 12;
    int l = bl & (L3LEN - 1);
    int t0 = g_tokens[((size_t)b * KCB + 0) * L3LEN + l];
    int t1 = g_tokens[((size_t)b * KCB + 1) * L3LEN + l];
    int t2 = g_tokens[((size_t)b * KCB + 2) * L3LEN + l];
    int t3 = g_tokens[((size_t)b * KCB + 3) * L3LEN + l];
    const float4* e0 = (const float4*)(embedding + (size_t)t0 * HID);
    const float4* e1 = (const float4*)(embedding + (size_t)t1 * HID);
    const float4* e2 = (const float4*)(embedding + (size_t)t2 * HID);
    const float4* e3 = (const float4*)(embedding + (size_t)t3 * HID);
    int h = threadIdx.x;
    float4 v0 = e0[h], v1 = e1[h], v2 = e2[h], v3 = e3[h];
    float4 rr;
    rr.x = 0.25f * (v0.x + v1.x + v2.x + v3.x);
    rr.y = 0.25f * (v0.y + v1.y + v2.y + v3.y);
    rr.z = 0.25f * (v0.z + v1.z + v2.z + v3.z);
    rr.w = 0.25f * (v0.w + v1.w + v2.w + v3.w);
    ((float4*)(out + ((size_t)b * L3LEN + l) * HID))[h] = rr;
}

__global__ void tok2f_kernel(float* __restrict__ out) {
    int i = blockIdx.x * blockDim.x + threadIdx.x;
    if (i < NTOK) out[i] = (float)g_tokens[i];
}

// ==================== launch ====================
extern "C" void kernel_launch(void* const* d_in, const int* in_sizes, int n_in,
                              void* d_out, int out_size) {
    const float* audio = 0; const float* w1 = 0; const float* b1 = 0;
    const float* w2 = 0; const float* b2 = 0; const float* w3 = 0; const float* b3 = 0;
    const float* codebook = 0; const float* embedding = 0;
    for (int i = 0; i < n_in; i++) {
        const float* p = (const float*)d_in[i];
        switch (in_sizes[i]) {
            case BATCH * SLEN:      audio = p; break;
            case C1 * 1 * 7:        w1 = p; break;
            case C1:                b1 = p; break;
            case C2 * C1 * 7:       w2 = p; break;
            case C2:                b2 = p; break;
            case HID * C2 * 7:      w3 = p; break;
            case HID:               b3 = p; break;
            case KCB * VOCAB * HID: codebook = p; break;
            case VOCAB * HID:       embedding = p; break;
            default: break;
        }
    }

    cudaFuncSetAttribute(gemm_hi_kernel,
                         cudaFuncAttributeMaxDynamicSharedMemorySize, ST_TOTAL);

    // order chosen so the 4th launch (ncu capture slot) = conv_fast<stage2>
    {
        dim3 grid(L1LEN / 64, BATCH);
        conv1_fast_kernel<<<grid, 256>>>(audio, w1, b1);
    }
    wtrans_kernel<C1, C2, 2><<<(C1 * C2 * 7 + 255) / 256, 256>>>(w2);
    wtrans_kernel<C2, HID, 3><<<(C2 * HID * 7 + 255) / 256, 256>>>(w3);
    {
        dim3 grid(L2LEN / 64, C2 / 128, BATCH);
        conv_fast_kernel<C1, C2, L2LEN, true, false, 2><<<grid, 256>>>(b2);
    }
    {
        dim3 grid(L3LEN / 64, HID / 128, BATCH);
        conv_fast_kernel<C2, HID, L3LEN, false, true, 3><<<grid, 256>>>(b3);
    }
    split_cb_kernel<<<(KCB * VOCAB * HID) / 256, 256>>>(codebook);
    c2_kernel<<<(KCB * VOCAB) / 8, 256>>>(codebook);
    cbmax_kernel<<<KCB, 256>>>();
    split_feats_kernel<<<(BATCH * L3LEN * HID) / 256, 256>>>();

    {
        dim3 grid(L3LEN / 128, VOCAB / 256, KCB * BATCH);
        gemm_hi_kernel<<<grid, 256, ST_TOTAL>>>();
    }
    select_kernel<<<NTOK / 8, 256>>>(codebook);

    const int TOK = NTOK;
    const int EMB = BATCH * L3LEN * HID;
    float* out = (float*)d_out;
    if (out_size >= TOK + EMB) {
        tok2f_kernel<<<(TOK + 255) / 256, 256>>>(out);
        emb_kernel<<<BATCH * L3LEN, 128>>>(embedding, out + TOK);
    } else if (out_size >= EMB) {
        emb_kernel<<<BATCH * L3LEN, 128>>>(embedding, out);
    } else {
        tok2f_kernel<<<(TOK + 255) / 256, 256>>>(out);
    }
}

// round 10
// speedup vs baseline: 1.1109x; 1.1109x over previous
#include <cuda_runtime.h>
#include <cuda_bf16.h>
#include <cuda_fp16.h>
#include <math_constants.h>
#include <cstdint>

// Problem constants
#define BATCH 4
#define SLEN  32768
#define C1    128
#define C2    256
#define HID   512
#define L1LEN 16384
#define L2LEN 8192
#define L3LEN 4096
#define VOCAB 2048
#define KCB   4
#define NTOK  (BATCH * KCB * L3LEN)      // 65536

// ------------------- device scratch (device-code references ONLY) -------------------
__device__ __align__(16) float g_conv1[BATCH * C1 * L1LEN];
__device__ __align__(16) float g_conv2[BATCH * C2 * L2LEN];
__device__ __align__(16) float g_feats[BATCH * L3LEN * HID];       // fp32 exact
__device__ __align__(16) float g_w2t[C2 * C1 * 7];                 // [(ci*7+t)][co]
__device__ __align__(16) float g_w3t[HID * C2 * 7];
__device__ __align__(16) __nv_bfloat16 g_fhi[BATCH * L3LEN * HID];
__device__ __align__(16) __nv_bfloat16 g_chi[KCB * VOCAB * HID];
__device__ __align__(16) __half g_cross[(size_t)NTOK * VOCAB];     // 256MB approx cross
__device__ float g_c2[KCB * VOCAB];
__device__ float g_cbmax[KCB];
__device__ int   g_tokens[NTOK];

// ==================== packed fp32 helpers (FFMA2 path, sm_103) ====================
__device__ __forceinline__ uint64_t pk2(float lo, float hi) {
    uint64_t r; asm("mov.b64 %0, {%1, %2};" : "=l"(r) : "f"(lo), "f"(hi)); return r;
}
__device__ __forceinline__ void fma2(uint64_t& c, uint64_t a, uint64_t b) {
    asm("fma.rn.f32x2 %0, %1, %2, %0;" : "+l"(c) : "l"(a), "l"(b));
}
__device__ __forceinline__ float2 upk(uint64_t v) {
    float2 f; asm("mov.b64 {%0, %1}, %2;" : "=f"(f.x), "=f"(f.y) : "l"(v)); return f;
}

// ==================== weight transpose: w[co][ci][7] -> wt[(ci*7+t)][co] ====================
template <int CI, int CO, int STAGE>
__global__ void wtrans_kernel(const float* __restrict__ w) {
    float* wt = (STAGE == 2) ? g_w2t : g_w3t;
    int i = blockIdx.x * 256 + threadIdx.x;
    if (i >= CI * CO * 7) return;
    int co = i % CO;
    int row = i / CO;                 // ci*7 + t
    int ci = row / 7, t = row % 7;
    wt[i] = w[((size_t)co * CI + ci) * 7 + t];
}

// ==================== conv1: Cin=1, tile 64 l x 128 c ====================
__global__ __launch_bounds__(256) void conv1_fast_kernel(const float* __restrict__ x,
                                                         const float* __restrict__ w,
                                                         const float* __restrict__ bias) {
    __shared__ float a_s[136];
    int tid = threadIdx.x;
    int lane = tid & 31, lg = tid >> 5;
    int l0 = blockIdx.x * 64;
    int b = blockIdx.y;

    for (int p = tid; p < 133; p += 256) {
        int pg = 2 * l0 - 3 + p;
        a_s[p] = (pg >= 0 && pg < SLEN) ? x[(size_t)b * SLEN + pg] : 0.f;
    }
    __syncthreads();

    float wr[4][7], bv[4];
#pragma unroll
    for (int c = 0; c < 4; c++) {
        int ch = lane + 32 * c;
        bv[c] = bias[ch];
#pragma unroll
        for (int t = 0; t < 7; t++) wr[c][t] = w[ch * 7 + t];
    }

    float xv[21];
#pragma unroll
    for (int p = 0; p < 21; p++) xv[p] = a_s[16 * lg + p];

    float acc[4][8];
#pragma unroll
    for (int c = 0; c < 4; c++)
#pragma unroll
        for (int j = 0; j < 8; j++) acc[c][j] = bv[c];
#pragma unroll
    for (int t = 0; t < 7; t++) {
#pragma unroll
        for (int j = 0; j < 8; j++) {
            float xx = xv[2 * j + t];
#pragma unroll
            for (int c = 0; c < 4; c++)
                acc[c][j] = fmaf(wr[c][t], xx, acc[c][j]);
        }
    }
#pragma unroll
    for (int c = 0; c < 4; c++) {
        int ch = lane + 32 * c;
#pragma unroll
        for (int j = 0; j < 8; j++) {
            int l = l0 + lg * 8 + j;
            g_conv1[((size_t)b * C1 + ch) * L1LEN + l] = fmaxf(acc[c][j], 0.f);
        }
    }
}

// ==================== conv2/3: tile 64 l x 128 co, thread 4co x 8l, FFMA2 ====================
template <int CI, int CO, int LOUT, bool RELU, bool TRANS_OUT, int STAGE>
__global__ __launch_bounds__(256, 2) void conv_fast_kernel(const float* __restrict__ bias) {
    const float* in  = (STAGE == 2) ? g_conv1 : g_conv2;
    const float* wT  = (STAGE == 2) ? g_w2t : g_w3t;
    float*       out = (STAGE == 2) ? g_conv2 : g_feats;

    const int LIN = 2 * LOUT;
    __shared__ __align__(16) float in_s[8][136];
    __shared__ __align__(16) float w_s[56 * 128];

    int tid = threadIdx.x;
    int lane = tid & 31, lg = tid >> 5;
    int l0  = blockIdx.x * 64;
    int co0 = blockIdx.y * 128;
    int b   = blockIdx.z;

    // acc2[cp][j] = packed (acc[2cp][j], acc[2cp+1][j]) where c -> co0 + lane + 32c
    uint64_t acc2[2][8];
#pragma unroll
    for (int cp = 0; cp < 2; cp++)
#pragma unroll
        for (int j = 0; j < 8; j++) acc2[cp][j] = 0ull;

    for (int ci0 = 0; ci0 < CI; ci0 += 8) {
        __syncthreads();
        for (int i = tid; i < 8 * 136; i += 256) {
            int ci = i / 136, p = i % 136;
            int pg = 2 * l0 - 3 + p;
            float v = 0.f;
            if (p < 133 && pg >= 0 && pg < LIN)
                v = in[((size_t)b * CI + ci0 + ci) * LIN + pg];
            in_s[ci][p] = v;
        }
        for (int i = tid; i < 56 * 128; i += 256) {
            int row = i >> 7, c = i & 127;
            w_s[i] = wT[(size_t)(ci0 * 7 + row) * CO + co0 + c];
        }
        __syncthreads();

#pragma unroll
        for (int ci = 0; ci < 8; ci++) {
            // xv via 6x LDS.128 (rows are 16B-aligned: 136*4 = 544 = 34*16)
            float xvf[24];
            const float4* xr = (const float4*)&in_s[ci][16 * lg];
#pragma unroll
            for (int q = 0; q < 6; q++) {
                float4 v = xr[q];
                xvf[4 * q] = v.x; xvf[4 * q + 1] = v.y;
                xvf[4 * q + 2] = v.z; xvf[4 * q + 3] = v.w;
            }
            uint64_t xd[21];
#pragma unroll
            for (int p = 0; p < 21; p++) xd[p] = pk2(xvf[p], xvf[p]);

#pragma unroll
            for (int t = 0; t < 7; t++) {
                const float* wrow = &w_s[(ci * 7 + t) * 128];
                uint64_t wp0 = pk2(wrow[lane],      wrow[lane + 32]);
                uint64_t wp1 = pk2(wrow[lane + 64], wrow[lane + 96]);
#pragma unroll
                for (int j = 0; j < 8; j++) {
                    fma2(acc2[0][j], wp0, xd[2 * j + t]);
                    fma2(acc2[1][j], wp1, xd[2 * j + t]);
                }
            }
        }
    }

#pragma unroll
    for (int cp = 0; cp < 2; cp++) {
#pragma unroll
        for (int half = 0; half < 2; half++) {
            int c = cp * 2 + half;
            int co = co0 + lane + 32 * c;
            float bv = bias[co];
#pragma unroll
            for (int j = 0; j < 8; j++) {
                float2 a = upk(acc2[cp][j]);
                float r = (half == 0 ? a.x : a.y) + bv;
                if (RELU) r = fmaxf(r, 0.f);
                int l = l0 + lg * 8 + j;
                if (TRANS_OUT)
                    out[((size_t)b * LOUT + l) * CO + co] = r;
                else
                    out[((size_t)b * CO + co) * LOUT + l] = r;
            }
        }
    }
}

// ==================== bf16 hi conversions ====================
__global__ void split_feats_kernel() {
    int i = blockIdx.x * blockDim.x + threadIdx.x;
    if (i >= BATCH * L3LEN * HID) return;
    g_fhi[i] = __float2bfloat16_rn(g_feats[i]);
}
__global__ void split_cb_kernel(const float* __restrict__ cb) {
    int i = blockIdx.x * blockDim.x + threadIdx.x;
    if (i >= KCB * VOCAB * HID) return;
    g_chi[i] = __float2bfloat16_rn(cb[i]);
}

// ==================== c2 + per-codebook max norm ====================
__global__ void c2_kernel(const float* __restrict__ cb) {
    int row = blockIdx.x * 8 + (threadIdx.x >> 5);
    int lane = threadIdx.x & 31;
    const float* p = cb + (size_t)row * HID;
    float s = 0.f;
#pragma unroll 4
    for (int h = lane; h < HID; h += 32) {
        float v = p[h];
        s = fmaf(v, v, s);
    }
#pragma unroll
    for (int off = 16; off; off >>= 1)
        s += __shfl_xor_sync(0xffffffffu, s, off);
    if (lane == 0) g_c2[row] = s;
}

__global__ void cbmax_kernel() {
    __shared__ float red[256];
    int k = blockIdx.x;
    float m = 0.f;
    for (int v = threadIdx.x; v < VOCAB; v += 256)
        m = fmaxf(m, g_c2[k * VOCAB + v]);
    red[threadIdx.x] = m;
    __syncthreads();
    for (int s = 128; s; s >>= 1) {
        if (threadIdx.x < s) red[threadIdx.x] = fmaxf(red[threadIdx.x], red[threadIdx.x + s]);
        __syncthreads();
    }
    if (threadIdx.x == 0) g_cbmax[k] = sqrtf(red[0]);
}

// ==================== stage 1: pure bf16 hi GEMM -> fp16 cross ====================
#define ST_A 0
#define ST_B 18432
#define ST_STRIDE 55296        // A(128x144) + B(256x144)
#define ST_TOTAL 110592

__device__ __forceinline__ uint32_t smem_u32(const void* p) {
    uint32_t a;
    asm("{ .reg .u64 t; cvta.to.shared.u64 t, %1; cvt.u32.u64 %0, t; }" : "=r"(a) : "l"(p));
    return a;
}
__device__ __forceinline__ void cp_async16(uint32_t s, const void* g) {
    asm volatile("cp.async.cg.shared.global [%0], [%1], 16;" :: "r"(s), "l"(g) : "memory");
}
__device__ __forceinline__ void mma_bf16(float* c, const uint32_t* a, const uint32_t* b0, const uint32_t* b1) {
    asm volatile(
        "mma.sync.aligned.m16n8k16.row.col.f32.bf16.bf16.f32 "
        "{%0,%1,%2,%3}, {%4,%5,%6,%7}, {%8,%9}, {%0,%1,%2,%3};"
        : "+f"(c[0]), "+f"(c[1]), "+f"(c[2]), "+f"(c[3])
        : "r"(a[0]), "r"(a[1]), "r"(a[2]), "r"(a[3]), "r"(*b0), "r"(*b1));
}
__device__ __forceinline__ void ldsm_x4(uint32_t* r, uint32_t addr) {
    asm volatile("ldmatrix.sync.aligned.m8n8.x4.shared.b16 {%0,%1,%2,%3}, [%4];"
                 : "=r"(r[0]), "=r"(r[1]), "=r"(r[2]), "=r"(r[3]) : "r"(addr));
}

__global__ __launch_bounds__(256, 1) void gemm_hi_kernel() {
    extern __shared__ char smem[];
    uint32_t sbase = smem_u32(smem);

    const int tid = threadIdx.x;
    const int wid = tid >> 5, lane = tid & 31;
    const int wm = wid >> 2, wn = wid & 3;
    const int g = lane >> 2, t = lane & 3;
    const int lt = blockIdx.x;
    const int vt = blockIdx.y;
    const int bk = blockIdx.z;
    const int b = bk >> 2, k = bk & 3;

    const __nv_bfloat16* A  = g_fhi + ((size_t)b * L3LEN + lt * 128) * HID;
    const __nv_bfloat16* Bm = g_chi + ((size_t)k * VOCAB + vt * 256) * HID;

    auto load_chunk = [&](int kc, int s) {
        uint32_t st = sbase + s * ST_STRIDE;
#pragma unroll
        for (int j = 0; j < 12; j++) {
            int idx = tid + j * 256;
            if (idx < 1024) {
                int r = idx >> 3, q = idx & 7;
                cp_async16(st + ST_A + r * 144 + q * 16,
                           A + (size_t)r * HID + kc * 64 + q * 8);
            } else {
                int i2 = idx - 1024;
                int r = i2 >> 3, q = i2 & 7;
                cp_async16(st + ST_B + r * 144 + q * 16,
                           Bm + (size_t)r * HID + kc * 64 + q * 8);
            }
        }
        asm volatile("cp.async.commit_group;" ::: "memory");
    };

    int lrow = (lane & 7) + ((lane >> 3) & 1) * 8;
    int lcol = (lane >> 4) * 16;
    uint32_t a_ad[2][4], b_ad[2][4];
#pragma unroll
    for (int s = 0; s < 2; s++) {
#pragma unroll
        for (int mi = 0; mi < 4; mi++)
            a_ad[s][mi] = sbase + s * ST_STRIDE + ST_A +
                          (wm * 64 + mi * 16 + lrow) * 144 + lcol;
#pragma unroll
        for (int j = 0; j < 4; j++)
            b_ad[s][j] = sbase + s * ST_STRIDE + ST_B +
                         (wn * 64 + j * 16 + lrow) * 144 + lcol;
    }

    float acc[4][8][4];
#pragma unroll
    for (int mi = 0; mi < 4; mi++)
#pragma unroll
        for (int ni = 0; ni < 8; ni++)
#pragma unroll
            for (int j = 0; j < 4; j++) acc[mi][ni][j] = 0.f;

    load_chunk(0, 0);
    for (int kc = 0; kc < 8; kc++) {
        if (kc < 7) {
            load_chunk(kc + 1, (kc + 1) & 1);
            asm volatile("cp.async.wait_group 1;" ::: "memory");
        } else {
            asm volatile("cp.async.wait_group 0;" ::: "memory");
        }
        __syncthreads();
        int st = kc & 1;
#pragma unroll
        for (int ks = 0; ks < 4; ks++) {
            uint32_t af[4][4], bfv[4][4];
#pragma unroll
            for (int mi = 0; mi < 4; mi++) ldsm_x4(af[mi], a_ad[st][mi] + ks * 32);
#pragma unroll
            for (int j = 0; j < 4; j++)  ldsm_x4(bfv[j], b_ad[st][j] + ks * 32);
#pragma unroll
            for (int j = 0; j < 4; j++) {
#pragma unroll
                for (int mi = 0; mi < 4; mi++) {
                    mma_bf16(acc[mi][2 * j],     af[mi], &bfv[j][0], &bfv[j][2]);
                    mma_bf16(acc[mi][2 * j + 1], af[mi], &bfv[j][1], &bfv[j][3]);
                }
            }
        }
        __syncthreads();
    }

#pragma unroll
    for (int mi = 0; mi < 4; mi++) {
        int row = lt * 128 + wm * 64 + mi * 16 + g;
        size_t code = (size_t)(b * KCB + k) * L3LEN + row;
        __half* out0 = g_cross + code * VOCAB;
        __half* out1 = g_cross + (code + 8) * VOCAB;
#pragma unroll
        for (int ni = 0; ni < 8; ni++) {
            int col = vt * 256 + wn * 64 + ni * 8 + 2 * t;
            *(__half2*)(out0 + col) = __floats2half2_rn(acc[mi][ni][0], acc[mi][ni][1]);
            *(__half2*)(out1 + col) = __floats2half2_rn(acc[mi][ni][2], acc[mi][ni][3]);
        }
    }
}

// ==================== stage 2: per-token select + bounded exact rescore ====================
__device__ __forceinline__ void upd_min(float& m, float& m2, int& idx, float d, int v) {
    if (d < m)       { m2 = m; m = d; idx = v; }
    else if (d < m2) { m2 = d; }
}
__device__ __forceinline__ void merge_min(float& m, float& m2, int& idx,
                                          float om, float om2, int oidx) {
    if (om < m) { m2 = fminf(m, om2); m = om; idx = oidx; }
    else        { m2 = fminf(m2, om); }
}

__global__ __launch_bounds__(256) void select_kernel(const float* __restrict__ cb) {
    __shared__ float c2_s[VOCAB];
    int tid = threadIdx.x;
    int wid = tid >> 5, lane = tid & 31;
    int code0 = blockIdx.x * 8;
    int k = (code0 >> 12) & (KCB - 1);

    for (int i = tid; i < VOCAB; i += 256)
        c2_s[i] = g_c2[k * VOCAB + i];
    __syncthreads();

    int code = code0 + wid;
    int l = code & (L3LEN - 1);
    int b = code >> 14;
    const __half2* crow2 = (const __half2*)(g_cross + (size_t)code * VOCAB);

    float minv = CUDART_INF_F, min2 = CUDART_INF_F;
    int mini = 0;
#pragma unroll 4
    for (int i = 0; i < 32; i++) {
        __half2 h = crow2[i * 32 + lane];
        int v = i * 64 + lane * 2;
        float d0 = c2_s[v]     - 2.f * __low2float(h);
        float d1 = c2_s[v + 1] - 2.f * __high2float(h);
        upd_min(minv, min2, mini, d0, v);
        upd_min(minv, min2, mini, d1, v + 1);
    }
#pragma unroll
    for (int off = 16; off; off >>= 1) {
        float om  = __shfl_xor_sync(0xffffffffu, minv, off);
        float om2 = __shfl_xor_sync(0xffffffffu, min2, off);
        int   oi  = __shfl_xor_sync(0xffffffffu, mini, off);
        merge_min(minv, min2, mini, om, om2, oi);
    }

    const float* f = g_feats + ((size_t)b * L3LEN + l) * HID;
    float fr[16];
    float n2 = 0.f;
#pragma unroll
    for (int j = 0; j < 16; j++) {
        fr[j] = f[j * 32 + lane];
        n2 = fmaf(fr[j], fr[j], n2);
    }
#pragma unroll
    for (int off = 16; off; off >>= 1)
        n2 += __shfl_xor_sync(0xffffffffu, n2, off);

    float TH = 0.009f * sqrtf(n2) * g_cbmax[k] + 1.0f;

    if (min2 - minv > TH) {
        if (lane == 0) g_tokens[code] = mini;
        return;
    }

    float thr = minv + TH;
    float bestd = CUDART_INF_F;
    int besti = VOCAB;
    for (int i = 0; i < 32; i++) {
        __half2 h = crow2[i * 32 + lane];
        int v = i * 64 + lane * 2;
        float d0 = c2_s[v]     - 2.f * __low2float(h);
        float d1 = c2_s[v + 1] - 2.f * __high2float(h);
        unsigned m0 = __ballot_sync(0xffffffffu, d0 <= thr);
        unsigned m1 = __ballot_sync(0xffffffffu, d1 <= thr);
        while (m0 | m1) {
            int s0 = m0 ? (__ffs(m0) - 1) : 33;
            int s1 = m1 ? (__ffs(m1) - 1) : 33;
            int vc;
            if (s0 <= s1) { vc = i * 64 + s0 * 2;     m0 &= m0 - 1; }
            else          { vc = i * 64 + s1 * 2 + 1; m1 &= m1 - 1; }
            const float* c = cb + ((size_t)k * VOCAB + vc) * HID;
            float dot = 0.f;
#pragma unroll
            for (int j = 0; j < 16; j++)
                dot = fmaf(fr[j], c[j * 32 + lane], dot);
#pragma unroll
            for (int off = 16; off; off >>= 1)
                dot += __shfl_xor_sync(0xffffffffu, dot, off);
            float de = c2_s[vc] - 2.f * dot;
            if (de < bestd || (de == bestd && vc < besti)) { bestd = de; besti = vc; }
        }
    }
    if (lane == 0) g_tokens[code] = besti;
}

// ==================== outputs ====================
__global__ void emb_kernel(const float* __restrict__ embedding, float* __restrict__ out) {
    int bl = blockIdx.x;
    int b = bl >> 12;
    int l = bl & (L3LEN - 1);
    int t0 = g_tokens[((size_t)b * KCB + 0) * L3LEN + l];
    int t1 = g_tokens[((size_t)b * KCB + 1) * L3LEN + l];
    int t2 = g_tokens[((size_t)b * KCB + 2) * L3LEN + l];
    int t3 = g_tokens[((size_t)b * KCB + 3) * L3LEN + l];
    const float4* e0 = (const float4*)(embedding + (size_t)t0 * HID);
    const float4* e1 = (const float4*)(embedding + (size_t)t1 * HID);
    const float4* e2 = (const float4*)(embedding + (size_t)t2 * HID);
    const float4* e3 = (const float4*)(embedding + (size_t)t3 * HID);
    int h = threadIdx.x;
    float4 v0 = e0[h], v1 = e1[h], v2 = e2[h], v3 = e3[h];
    float4 rr;
    rr.x = 0.25f * (v0.x + v1.x + v2.x + v3.x);
    rr.y = 0.25f * (v0.y + v1.y + v2.y + v3.y);
    rr.z = 0.25f * (v0.z + v1.z + v2.z + v3.z);
    rr.w = 0.25f * (v0.w + v1.w + v2.w + v3.w);
    ((float4*)(out + ((size_t)b * L3LEN + l) * HID))[h] = rr;
}

__global__ void tok2f_kernel(float* __restrict__ out) {
    int i = blockIdx.x * blockDim.x + threadIdx.x;
    if (i < NTOK) out[i] = (float)g_tokens[i];
}

// ==================== launch ====================
extern "C" void kernel_launch(void* const* d_in, const int* in_sizes, int n_in,
                              void* d_out, int out_size) {
    const float* audio = 0; const float* w1 = 0; const float* b1 = 0;
    const float* w2 = 0; const float* b2 = 0; const float* w3 = 0; const float* b3 = 0;
    const float* codebook = 0; const float* embedding = 0;
    for (int i = 0; i < n_in; i++) {
        const float* p = (const float*)d_in[i];
        switch (in_sizes[i]) {
            case BATCH * SLEN:      audio = p; break;
            case C1 * 1 * 7:        w1 = p; break;
            case C1:                b1 = p; break;
            case C2 * C1 * 7:       w2 = p; break;
            case C2:                b2 = p; break;
            case HID * C2 * 7:      w3 = p; break;
            case HID:               b3 = p; break;
            case KCB * VOCAB * HID: codebook = p; break;
            case VOCAB * HID:       embedding = p; break;
            default: break;
        }
    }

    cudaFuncSetAttribute(gemm_hi_kernel,
                         cudaFuncAttributeMaxDynamicSharedMemorySize, ST_TOTAL);

    // order chosen so the 4th launch (ncu capture slot) = conv_fast<stage2>
    {
        dim3 grid(L1LEN / 64, BATCH);
        conv1_fast_kernel<<<grid, 256>>>(audio, w1, b1);
    }
    wtrans_kernel<C1, C2, 2><<<(C1 * C2 * 7 + 255) / 256, 256>>>(w2);
    wtrans_kernel<C2, HID, 3><<<(C2 * HID * 7 + 255) / 256, 256>>>(w3);
    {
        dim3 grid(L2LEN / 64, C2 / 128, BATCH);
        conv_fast_kernel<C1, C2, L2LEN, true, false, 2><<<grid, 256>>>(b2);
    }
    {
        dim3 grid(L3LEN / 64, HID / 128, BATCH);
        conv_fast_kernel<C2, HID, L3LEN, false, true, 3><<<grid, 256>>>(b3);
    }
    split_cb_kernel<<<(KCB * VOCAB * HID) / 256, 256>>>(codebook);
    c2_kernel<<<(KCB * VOCAB) / 8, 256>>>(codebook);
    cbmax_kernel<<<KCB, 256>>>();
    split_feats_kernel<<<(BATCH * L3LEN * HID) / 256, 256>>>();

    {
        dim3 grid(L3LEN / 128, VOCAB / 256, KCB * BATCH);
        gemm_hi_kernel<<<grid, 256, ST_TOTAL>>>();
    }
    select_kernel<<<NTOK / 8, 256>>>(codebook);

    const int TOK = NTOK;
    const int EMB = BATCH * L3LEN * HID;
    float* out = (float*)d_out;
    if (out_size >= TOK + EMB) {
        tok2f_kernel<<<(TOK + 255) / 256, 256>>>(out);
        emb_kernel<<<BATCH * L3LEN, 128>>>(embedding, out + TOK);
    } else if (out_size >= EMB) {
        emb_kernel<<<BATCH * L3LEN, 128>>>(embedding, out);
    } else {
        tok2f_kernel<<<(TOK + 255) / 256, 256>>>(out);
    }
}

// round 11
// speedup vs baseline: 1.2644x; 1.1382x over previous
#include <cuda_runtime.h>
#include <cuda_bf16.h>
#include <cuda_fp16.h>
#include <math_constants.h>
#include <cstdint>
#include <cstring>

// Problem constants
#define BATCH 4
#define SLEN  32768
#define C1    128
#define C2    256
#define HID   512
#define L1LEN 16384
#define L2LEN 8192
#define L3LEN 4096
#define VOCAB 2048
#define KCB   4
#define NTOK  (BATCH * KCB * L3LEN)      // 65536

// ------------------- device scratch (device-code references ONLY) -------------------
__device__ __align__(16) float g_conv1[BATCH * C1 * L1LEN];
__device__ __align__(16) float g_conv2[BATCH * C2 * L2LEN];
__device__ __align__(16) float g_feats[BATCH * L3LEN * HID];       // fp32 exact
__device__ __align__(16) float g_w2t[C2 * C1 * 7];                 // [(ci*7+t)][co]
__device__ __align__(16) float g_w3t[HID * C2 * 7];
__device__ __align__(16) __nv_bfloat16 g_fhi[BATCH * L3LEN * HID];
__device__ __align__(16) __nv_bfloat16 g_chi[KCB * VOCAB * HID];
__device__ __align__(16) __half g_cross[(size_t)NTOK * VOCAB];     // 256MB approx cross
__device__ float g_c2[KCB * VOCAB];
__device__ float g_cbmax[KCB];
__device__ int   g_tokens[NTOK];

// ==================== packed fp32 helpers (FFMA2 path, sm_103) ====================
__device__ __forceinline__ uint64_t pk2(float lo, float hi) {
    uint64_t r; asm("mov.b64 %0, {%1, %2};" : "=l"(r) : "f"(lo), "f"(hi)); return r;
}
__device__ __forceinline__ uint64_t pkdup(float v) {
    uint64_t r; asm("mov.b64 %0, {%1, %1};" : "=l"(r) : "f"(v)); return r;
}
__device__ __forceinline__ void fma2(uint64_t& c, uint64_t a, uint64_t b) {
    asm("fma.rn.f32x2 %0, %1, %2, %0;" : "+l"(c) : "l"(a), "l"(b));
}
__device__ __forceinline__ float2 upk(uint64_t v) {
    float2 f; asm("mov.b64 {%0, %1}, %2;" : "=f"(f.x), "=f"(f.y) : "l"(v)); return f;
}

// ==================== weight transpose: w[co][ci][7] -> wt[(ci*7+t)][co] ====================
template <int CI, int CO, int STAGE>
__global__ void wtrans_kernel(const float* __restrict__ w) {
    float* wt = (STAGE == 2) ? g_w2t : g_w3t;
    int i = blockIdx.x * 256 + threadIdx.x;
    if (i >= CI * CO * 7) return;
    int co = i % CO;
    int row = i / CO;                 // ci*7 + t
    int ci = row / 7, t = row % 7;
    wt[i] = w[((size_t)co * CI + ci) * 7 + t];
}

// ==================== conv1: Cin=1, tile 64 l x 128 c ====================
__global__ __launch_bounds__(256) void conv1_fast_kernel(const float* __restrict__ x,
                                                         const float* __restrict__ w,
                                                         const float* __restrict__ bias) {
    __shared__ float a_s[136];
    int tid = threadIdx.x;
    int lane = tid & 31, lg = tid >> 5;
    int l0 = blockIdx.x * 64;
    int b = blockIdx.y;

    for (int p = tid; p < 133; p += 256) {
        int pg = 2 * l0 - 3 + p;
        a_s[p] = (pg >= 0 && pg < SLEN) ? x[(size_t)b * SLEN + pg] : 0.f;
    }
    __syncthreads();

    float wr[4][7], bv[4];
#pragma unroll
    for (int c = 0; c < 4; c++) {
        int ch = lane + 32 * c;
        bv[c] = bias[ch];
#pragma unroll
        for (int t = 0; t < 7; t++) wr[c][t] = w[ch * 7 + t];
    }

    float xv[21];
#pragma unroll
    for (int p = 0; p < 21; p++) xv[p] = a_s[16 * lg + p];

    float acc[4][8];
#pragma unroll
    for (int c = 0; c < 4; c++)
#pragma unroll
        for (int j = 0; j < 8; j++) acc[c][j] = bv[c];
#pragma unroll
    for (int t = 0; t < 7; t++) {
#pragma unroll
        for (int j = 0; j < 8; j++) {
            float xx = xv[2 * j + t];
#pragma unroll
            for (int c = 0; c < 4; c++)
                acc[c][j] = fmaf(wr[c][t], xx, acc[c][j]);
        }
    }
#pragma unroll
    for (int c = 0; c < 4; c++) {
        int ch = lane + 32 * c;
#pragma unroll
        for (int j = 0; j < 8; j++) {
            int l = l0 + lg * 8 + j;
            g_conv1[((size_t)b * C1 + ch) * L1LEN + l] = fmaxf(acc[c][j], 0.f);
        }
    }
}

// ==================== conv2/3: tile 64 l x 128 co, FFMA2, paired-weight SMEM ====================
// acc2[0][j] packs co=(lane, lane+32); acc2[1][j] packs (lane+64, lane+96).
// w2_s[row][p]: p<32 -> (w[p], w[p+32]); p>=32 -> (w[p+32], w[p+64]).
template <int CI, int CO, int LOUT, bool RELU, bool TRANS_OUT, int STAGE>
__global__ __launch_bounds__(256, 3) void conv_fast_kernel(const float* __restrict__ bias) {
    const float* in  = (STAGE == 2) ? g_conv1 : g_conv2;
    const float* wT  = (STAGE == 2) ? g_w2t : g_w3t;
    float*       out = (STAGE == 2) ? g_conv2 : g_feats;

    const int LIN = 2 * LOUT;
    __shared__ __align__(16) float  in_s[8][136];
    __shared__ __align__(16) float2 w2_s[56 * 64];

    int tid = threadIdx.x;
    int lane = tid & 31, lg = tid >> 5;
    int l0  = blockIdx.x * 64;
    int co0 = blockIdx.y * 128;
    int b   = blockIdx.z;

    uint64_t acc2[2][8];
#pragma unroll
    for (int cp = 0; cp < 2; cp++)
#pragma unroll
        for (int j = 0; j < 8; j++) acc2[cp][j] = 0ull;

    for (int ci0 = 0; ci0 < CI; ci0 += 8) {
        __syncthreads();
        for (int i = tid; i < 8 * 136; i += 256) {
            int ci = i / 136, p = i % 136;
            int pg = 2 * l0 - 3 + p;
            float v = 0.f;
            if (p < 133 && pg >= 0 && pg < LIN)
                v = in[((size_t)b * CI + ci0 + ci) * LIN + pg];
            in_s[ci][p] = v;
        }
        // paired weights: 56 rows x 64 float2
        for (int i = tid; i < 56 * 64; i += 256) {
            int row = i >> 6, p = i & 63;
            int c_lo = (p < 32) ? p : p + 32;
            const float* wr = wT + (size_t)(ci0 * 7 + row) * CO + co0;
            w2_s[i] = make_float2(wr[c_lo], wr[c_lo + 32]);
        }
        __syncthreads();

#pragma unroll
        for (int ci = 0; ci < 8; ci++) {
            float xvf[24];
            const float4* xr = (const float4*)&in_s[ci][16 * lg];
#pragma unroll
            for (int q = 0; q < 6; q++) {
                float4 v = xr[q];
                xvf[4 * q] = v.x; xvf[4 * q + 1] = v.y;
                xvf[4 * q + 2] = v.z; xvf[4 * q + 3] = v.w;
            }

#pragma unroll
            for (int t = 0; t < 7; t++) {
                float2 w0f = w2_s[(ci * 7 + t) * 64 + lane];
                float2 w1f = w2_s[(ci * 7 + t) * 64 + 32 + lane];
                uint64_t w0, w1;
                memcpy(&w0, &w0f, 8);
                memcpy(&w1, &w1f, 8);
#pragma unroll
                for (int j = 0; j < 8; j++) {
                    uint64_t xd = pkdup(xvf[2 * j + t]);
                    fma2(acc2[0][j], w0, xd);
                    fma2(acc2[1][j], w1, xd);
                }
            }
        }
    }

#pragma unroll
    for (int cp = 0; cp < 2; cp++) {
#pragma unroll
        for (int half = 0; half < 2; half++) {
            int c = cp * 2 + half;
            int co = co0 + lane + 32 * c;
            float bv = bias[co];
#pragma unroll
            for (int j = 0; j < 8; j++) {
                float2 a = upk(acc2[cp][j]);
                float r = (half == 0 ? a.x : a.y) + bv;
                if (RELU) r = fmaxf(r, 0.f);
                int l = l0 + lg * 8 + j;
                if (TRANS_OUT)
                    out[((size_t)b * LOUT + l) * CO + co] = r;
                else
                    out[((size_t)b * CO + co) * LOUT + l] = r;
            }
        }
    }
}

// ==================== bf16 hi conversions ====================
__global__ void split_feats_kernel() {
    int i = blockIdx.x * blockDim.x + threadIdx.x;
    if (i >= BATCH * L3LEN * HID) return;
    g_fhi[i] = __float2bfloat16_rn(g_feats[i]);
}
__global__ void split_cb_kernel(const float* __restrict__ cb) {
    int i = blockIdx.x * blockDim.x + threadIdx.x;
    if (i >= KCB * VOCAB * HID) return;
    g_chi[i] = __float2bfloat16_rn(cb[i]);
}

// ==================== c2 + per-codebook max norm ====================
__global__ void c2_kernel(const float* __restrict__ cb) {
    int row = blockIdx.x * 8 + (threadIdx.x >> 5);
    int lane = threadIdx.x & 31;
    const float* p = cb + (size_t)row * HID;
    float s = 0.f;
#pragma unroll 4
    for (int h = lane; h < HID; h += 32) {
        float v = p[h];
        s = fmaf(v, v, s);
    }
#pragma unroll
    for (int off = 16; off; off >>= 1)
        s += __shfl_xor_sync(0xffffffffu, s, off);
    if (lane == 0) g_c2[row] = s;
}

__global__ void cbmax_kernel() {
    __shared__ float red[256];
    int k = blockIdx.x;
    float m = 0.f;
    for (int v = threadIdx.x; v < VOCAB; v += 256)
        m = fmaxf(m, g_c2[k * VOCAB + v]);
    red[threadIdx.x] = m;
    __syncthreads();
    for (int s = 128; s; s >>= 1) {
        if (threadIdx.x < s) red[threadIdx.x] = fmaxf(red[threadIdx.x], red[threadIdx.x + s]);
        __syncthreads();
    }
    if (threadIdx.x == 0) g_cbmax[k] = sqrtf(red[0]);
}

// ==================== stage 1: pure bf16 hi GEMM -> fp16 cross ====================
#define ST_A 0
#define ST_B 18432
#define ST_STRIDE 55296        // A(128x144) + B(256x144)
#define ST_TOTAL 110592

__device__ __forceinline__ uint32_t smem_u32(const void* p) {
    uint32_t a;
    asm("{ .reg .u64 t; cvta.to.shared.u64 t, %1; cvt.u32.u64 %0, t; }" : "=r"(a) : "l"(p));
    return a;
}
__device__ __forceinline__ void cp_async16(uint32_t s, const void* g) {
    asm volatile("cp.async.cg.shared.global [%0], [%1], 16;" :: "r"(s), "l"(g) : "memory");
}
__device__ __forceinline__ void mma_bf16(float* c, const uint32_t* a, const uint32_t* b0, const uint32_t* b1) {
    asm volatile(
        "mma.sync.aligned.m16n8k16.row.col.f32.bf16.bf16.f32 "
        "{%0,%1,%2,%3}, {%4,%5,%6,%7}, {%8,%9}, {%0,%1,%2,%3};"
        : "+f"(c[0]), "+f"(c[1]), "+f"(c[2]), "+f"(c[3])
        : "r"(a[0]), "r"(a[1]), "r"(a[2]), "r"(a[3]), "r"(*b0), "r"(*b1));
}
__device__ __forceinline__ void ldsm_x4(uint32_t* r, uint32_t addr) {
    asm volatile("ldmatrix.sync.aligned.m8n8.x4.shared.b16 {%0,%1,%2,%3}, [%4];"
                 : "=r"(r[0]), "=r"(r[1]), "=r"(r[2]), "=r"(r[3]) : "r"(addr));
}

__global__ __launch_bounds__(256, 1) void gemm_hi_kernel() {
    extern __shared__ char smem[];
    uint32_t sbase = smem_u32(smem);

    const int tid = threadIdx.x;
    const int wid = tid >> 5, lane = tid & 31;
    const int wm = wid >> 2, wn = wid & 3;
    const int g = lane >> 2, t = lane & 3;
    const int lt = blockIdx.x;
    const int vt = blockIdx.y;
    const int bk = blockIdx.z;
    const int b = bk >> 2, k = bk & 3;

    const __nv_bfloat16* A  = g_fhi + ((size_t)b * L3LEN + lt * 128) * HID;
    const __nv_bfloat16* Bm = g_chi + ((size_t)k * VOCAB + vt * 256) * HID;

    auto load_chunk = [&](int kc, int s) {
        uint32_t st = sbase + s * ST_STRIDE;
#pragma unroll
        for (int j = 0; j < 12; j++) {
            int idx = tid + j * 256;
            if (idx < 1024) {
                int r = idx >> 3, q = idx & 7;
                cp_async16(st + ST_A + r * 144 + q * 16,
                           A + (size_t)r * HID + kc * 64 + q * 8);
            } else {
                int i2 = idx - 1024;
                int r = i2 >> 3, q = i2 & 7;
                cp_async16(st + ST_B + r * 144 + q * 16,
                           Bm + (size_t)r * HID + kc * 64 + q * 8);
            }
        }
        asm volatile("cp.async.commit_group;" ::: "memory");
    };

    int lrow = (lane & 7) + ((lane >> 3) & 1) * 8;
    int lcol = (lane >> 4) * 16;
    uint32_t a_ad[2][4], b_ad[2][4];
#pragma unroll
    for (int s = 0; s < 2; s++) {
#pragma unroll
        for (int mi = 0; mi < 4; mi++)
            a_ad[s][mi] = sbase + s * ST_STRIDE + ST_A +
                          (wm * 64 + mi * 16 + lrow) * 144 + lcol;
#pragma unroll
        for (int j = 0; j < 4; j++)
            b_ad[s][j] = sbase + s * ST_STRIDE + ST_B +
                         (wn * 64 + j * 16 + lrow) * 144 + lcol;
    }

    float acc[4][8][4];
#pragma unroll
    for (int mi = 0; mi < 4; mi++)
#pragma unroll
        for (int ni = 0; ni < 8; ni++)
#pragma unroll
            for (int j = 0; j < 4; j++) acc[mi][ni][j] = 0.f;

    load_chunk(0, 0);
    for (int kc = 0; kc < 8; kc++) {
        if (kc < 7) {
            load_chunk(kc + 1, (kc + 1) & 1);
            asm volatile("cp.async.wait_group 1;" ::: "memory");
        } else {
            asm volatile("cp.async.wait_group 0;" ::: "memory");
        }
        __syncthreads();
        int st = kc & 1;
#pragma unroll
        for (int ks = 0; ks < 4; ks++) {
            uint32_t af[4][4], bfv[4][4];
#pragma unroll
            for (int mi = 0; mi < 4; mi++) ldsm_x4(af[mi], a_ad[st][mi] + ks * 32);
#pragma unroll
            for (int j = 0; j < 4; j++)  ldsm_x4(bfv[j], b_ad[st][j] + ks * 32);
#pragma unroll
            for (int j = 0; j < 4; j++) {
#pragma unroll
                for (int mi = 0; mi < 4; mi++) {
                    mma_bf16(acc[mi][2 * j],     af[mi], &bfv[j][0], &bfv[j][2]);
                    mma_bf16(acc[mi][2 * j + 1], af[mi], &bfv[j][1], &bfv[j][3]);
                }
            }
        }
        __syncthreads();
    }

#pragma unroll
    for (int mi = 0; mi < 4; mi++) {
        int row = lt * 128 + wm * 64 + mi * 16 + g;
        size_t code = (size_t)(b * KCB + k) * L3LEN + row;
        __half* out0 = g_cross + code * VOCAB;
        __half* out1 = g_cross + (code + 8) * VOCAB;
#pragma unroll
        for (int ni = 0; ni < 8; ni++) {
            int col = vt * 256 + wn * 64 + ni * 8 + 2 * t;
            *(__half2*)(out0 + col) = __floats2half2_rn(acc[mi][ni][0], acc[mi][ni][1]);
            *(__half2*)(out1 + col) = __floats2half2_rn(acc[mi][ni][2], acc[mi][ni][3]);
        }
    }
}

// ==================== stage 2: per-token select + bounded exact rescore ====================
__device__ __forceinline__ void upd_min(float& m, float& m2, int& idx, float d, int v) {
    if (d < m)       { m2 = m; m = d; idx = v; }
    else if (d < m2) { m2 = d; }
}
__device__ __forceinline__ void merge_min(float& m, float& m2, int& idx,
                                          float om, float om2, int oidx) {
    if (om < m) { m2 = fminf(m, om2); m = om; idx = oidx; }
    else        { m2 = fminf(m2, om); }
}

__global__ __launch_bounds__(256) void select_kernel(const float* __restrict__ cb) {
    __shared__ float c2_s[VOCAB];
    int tid = threadIdx.x;
    int wid = tid >> 5, lane = tid & 31;
    int code0 = blockIdx.x * 8;
    int k = (code0 >> 12) & (KCB - 1);

    for (int i = tid; i < VOCAB; i += 256)
        c2_s[i] = g_c2[k * VOCAB + i];
    __syncthreads();

    int code = code0 + wid;
    int l = code & (L3LEN - 1);
    int b = code >> 14;
    const __half2* crow2 = (const __half2*)(g_cross + (size_t)code * VOCAB);

    float minv = CUDART_INF_F, min2 = CUDART_INF_F;
    int mini = 0;
#pragma unroll 4
    for (int i = 0; i < 32; i++) {
        __half2 h = crow2[i * 32 + lane];
        int v = i * 64 + lane * 2;
        float d0 = c2_s[v]     - 2.f * __low2float(h);
        float d1 = c2_s[v + 1] - 2.f * __high2float(h);
        upd_min(minv, min2, mini, d0, v);
        upd_min(minv, min2, mini, d1, v + 1);
    }
#pragma unroll
    for (int off = 16; off; off >>= 1) {
        float om  = __shfl_xor_sync(0xffffffffu, minv, off);
        float om2 = __shfl_xor_sync(0xffffffffu, min2, off);
        int   oi  = __shfl_xor_sync(0xffffffffu, mini, off);
        merge_min(minv, min2, mini, om, om2, oi);
    }

    const float* f = g_feats + ((size_t)b * L3LEN + l) * HID;
    float fr[16];
    float n2 = 0.f;
#pragma unroll
    for (int j = 0; j < 16; j++) {
        fr[j] = f[j * 32 + lane];
        n2 = fmaf(fr[j], fr[j], n2);
    }
#pragma unroll
    for (int off = 16; off; off >>= 1)
        n2 += __shfl_xor_sync(0xffffffffu, n2, off);

    float TH = 0.009f * sqrtf(n2) * g_cbmax[k] + 1.0f;

    if (min2 - minv > TH) {
        if (lane == 0) g_tokens[code] = mini;
        return;
    }

    float thr = minv + TH;
    float bestd = CUDART_INF_F;
    int besti = VOCAB;
    for (int i = 0; i < 32; i++) {
        __half2 h = crow2[i * 32 + lane];
        int v = i * 64 + lane * 2;
        float d0 = c2_s[v]     - 2.f * __low2float(h);
        float d1 = c2_s[v + 1] - 2.f * __high2float(h);
        unsigned m0 = __ballot_sync(0xffffffffu, d0 <= thr);
        unsigned m1 = __ballot_sync(0xffffffffu, d1 <= thr);
        while (m0 | m1) {
            int s0 = m0 ? (__ffs(m0) - 1) : 33;
            int s1 = m1 ? (__ffs(m1) - 1) : 33;
            int vc;
            if (s0 <= s1) { vc = i * 64 + s0 * 2;     m0 &= m0 - 1; }
            else          { vc = i * 64 + s1 * 2 + 1; m1 &= m1 - 1; }
            const float* c = cb + ((size_t)k * VOCAB + vc) * HID;
            float dot = 0.f;
#pragma unroll
            for (int j = 0; j < 16; j++)
                dot = fmaf(fr[j], c[j * 32 + lane], dot);
#pragma unroll
            for (int off = 16; off; off >>= 1)
                dot += __shfl_xor_sync(0xffffffffu, dot, off);
            float de = c2_s[vc] - 2.f * dot;
            if (de < bestd || (de == bestd && vc < besti)) { bestd = de; besti = vc; }
        }
    }
    if (lane == 0) g_tokens[code] = besti;
}

// ==================== outputs ====================
__global__ void emb_kernel(const float* __restrict__ embedding, float* __restrict__ out) {
    int bl = blockIdx.x;
    int b = bl >> 12;
    int l = bl & (L3LEN - 1);
    int t0 = g_tokens[((size_t)b * KCB + 0) * L3LEN + l];
    int t1 = g_tokens[((size_t)b * KCB + 1) * L3LEN + l];
    int t2 = g_tokens[((size_t)b * KCB + 2) * L3LEN + l];
    int t3 = g_tokens[((size_t)b * KCB + 3) * L3LEN + l];
    const float4* e0 = (const float4*)(embedding + (size_t)t0 * HID);
    const float4* e1 = (const float4*)(embedding + (size_t)t1 * HID);
    const float4* e2 = (const float4*)(embedding + (size_t)t2 * HID);
    const float4* e3 = (const float4*)(embedding + (size_t)t3 * HID);
    int h = threadIdx.x;
    float4 v0 = e0[h], v1 = e1[h], v2 = e2[h], v3 = e3[h];
    float4 rr;
    rr.x = 0.25f * (v0.x + v1.x + v2.x + v3.x);
    rr.y = 0.25f * (v0.y + v1.y + v2.y + v3.y);
    rr.z = 0.25f * (v0.z + v1.z + v2.z + v3.z);
    rr.w = 0.25f * (v0.w + v1.w + v2.w + v3.w);
    ((float4*)(out + ((size_t)b * L3LEN + l) * HID))[h] = rr;
}

__global__ void tok2f_kernel(float* __restrict__ out) {
    int i = blockIdx.x * blockDim.x + threadIdx.x;
    if (i < NTOK) out[i] = (float)g_tokens[i];
}

// ==================== launch ====================
extern "C" void kernel_launch(void* const* d_in, const int* in_sizes, int n_in,
                              void* d_out, int out_size) {
    const float* audio = 0; const float* w1 = 0; const float* b1 = 0;
    const float* w2 = 0; const float* b2 = 0; const float* w3 = 0; const float* b3 = 0;
    const float* codebook = 0; const float* embedding = 0;
    for (int i = 0; i < n_in; i++) {
        const float* p = (const float*)d_in[i];
        switch (in_sizes[i]) {
            case BATCH * SLEN:      audio = p; break;
            case C1 * 1 * 7:        w1 = p; break;
            case C1:                b1 = p; break;
            case C2 * C1 * 7:       w2 = p; break;
            case C2:                b2 = p; break;
            case HID * C2 * 7:      w3 = p; break;
            case HID:               b3 = p; break;
            case KCB * VOCAB * HID: codebook = p; break;
            case VOCAB * HID:       embedding = p; break;
            default: break;
        }
    }

    cudaFuncSetAttribute(gemm_hi_kernel,
                         cudaFuncAttributeMaxDynamicSharedMemorySize, ST_TOTAL);

    // order chosen so the 4th launch (ncu capture slot) = conv_fast<stage2>
    {
        dim3 grid(L1LEN / 64, BATCH);
        conv1_fast_kernel<<<grid, 256>>>(audio, w1, b1);
    }
    wtrans_kernel<C1, C2, 2><<<(C1 * C2 * 7 + 255) / 256, 256>>>(w2);
    wtrans_kernel<C2, HID, 3><<<(C2 * HID * 7 + 255) / 256, 256>>>(w3);
    {
        dim3 grid(L2LEN / 64, C2 / 128, BATCH);
        conv_fast_kernel<C1, C2, L2LEN, true, false, 2><<<grid, 256>>>(b2);
    }
    {
        dim3 grid(L3LEN / 64, HID / 128, BATCH);
        conv_fast_kernel<C2, HID, L3LEN, false, true, 3><<<grid, 256>>>(b3);
    }
    split_cb_kernel<<<(KCB * VOCAB * HID) / 256, 256>>>(codebook);
    c2_kernel<<<(KCB * VOCAB) / 8, 256>>>(codebook);
    cbmax_kernel<<<KCB, 256>>>();
    split_feats_kernel<<<(BATCH * L3LEN * HID) / 256, 256>>>();

    {
        dim3 grid(L3LEN / 128, VOCAB / 256, KCB * BATCH);
        gemm_hi_kernel<<<grid, 256, ST_TOTAL>>>();
    }
    select_kernel<<<NTOK / 8, 256>>>(codebook);

    const int TOK = NTOK;
    const int EMB = BATCH * L3LEN * HID;
    float* out = (float*)d_out;
    if (out_size >= TOK + EMB) {
        tok2f_kernel<<<(TOK + 255) / 256, 256>>>(out);
        emb_kernel<<<BATCH * L3LEN, 128>>>(embedding, out + TOK);
    } else if (out_size >= EMB) {
        emb_kernel<<<BATCH * L3LEN, 128>>>(embedding, out);
    } else {
        tok2f_kernel<<<(TOK + 255) / 256, 256>>>(out);
    }
}

// round 12
// speedup vs baseline: 1.4667x; 1.1600x over previous
#include <cuda_runtime.h>
#include <cuda_bf16.h>
#include <cuda_fp16.h>
#include <math_constants.h>
#include <cstdint>
#include <cstring>

// Problem constants
#define BATCH 4
#define SLEN  32768
#define C1    128
#define C2    256
#define HID   512
#define L1LEN 16384
#define L2LEN 8192
#define L3LEN 4096
#define VOCAB 2048
#define KCB   4
#define NTOK  (BATCH * KCB * L3LEN)      // 65536

// ------------------- device scratch (device-code references ONLY) -------------------
__device__ __align__(16) float g_conv1[BATCH * C1 * L1LEN];
__device__ __align__(16) float g_conv2[BATCH * C2 * L2LEN];
__device__ __align__(16) float g_feats[BATCH * L3LEN * HID];       // fp32 exact
__device__ __align__(16) float2 g_w2p[(C2 / 128) * (C1 / 8) * 56 * 64];   // packed pairs
__device__ __align__(16) float2 g_w3p[(HID / 128) * (C2 / 8) * 56 * 64];
__device__ __align__(16) __nv_bfloat16 g_fhi[BATCH * L3LEN * HID];
__device__ __align__(16) __nv_bfloat16 g_chi[KCB * VOCAB * HID];
__device__ __align__(16) __half g_cross[(size_t)NTOK * VOCAB];     // 256MB approx cross
__device__ float g_c2[KCB * VOCAB];
__device__ float g_cbmax[KCB];
__device__ int   g_tokens[NTOK];

// ==================== packed fp32 helpers (FFMA2 path, sm_103) ====================
__device__ __forceinline__ uint64_t pkdup(float v) {
    uint64_t r; asm("mov.b64 %0, {%1, %1};" : "=l"(r) : "f"(v)); return r;
}
__device__ __forceinline__ void fma2(uint64_t& c, uint64_t a, uint64_t b) {
    asm("fma.rn.f32x2 %0, %1, %2, %0;" : "+l"(c) : "l"(a), "l"(b));
}
__device__ __forceinline__ float2 upk(uint64_t v) {
    float2 f; asm("mov.b64 {%0, %1}, %2;" : "=f"(f.x), "=f"(f.y) : "l"(v)); return f;
}
__device__ __forceinline__ uint32_t smem_u32(const void* p) {
    uint32_t a;
    asm("{ .reg .u64 t; cvta.to.shared.u64 t, %1; cvt.u32.u64 %0, t; }" : "=r"(a) : "l"(p));
    return a;
}
__device__ __forceinline__ void cp_async16(uint32_t s, const void* g) {
    asm volatile("cp.async.cg.shared.global [%0], [%1], 16;" :: "r"(s), "l"(g) : "memory");
}
__device__ __forceinline__ void cp_async16z(uint32_t s, const void* g, int n) {
    asm volatile("cp.async.cg.shared.global [%0], [%1], 16, %2;" :: "r"(s), "l"(g), "r"(n) : "memory");
}
#define CP_COMMIT() asm volatile("cp.async.commit_group;" ::: "memory")
#define CP_WAIT0()  asm volatile("cp.async.wait_group 0;" ::: "memory")

// ==================== weight pack: w[co][ci][7] -> [cb][chunk][row56][pair64] ====================
template <int CI, int CO, int STAGE>
__global__ void wpack_kernel(const float* __restrict__ w) {
    float2* wp = (STAGE == 2) ? g_w2p : g_w3p;
    const int TOTAL = (CO / 128) * (CI / 8) * 56 * 64;
    int i = blockIdx.x * 256 + threadIdx.x;
    if (i >= TOTAL) return;
    int p = i & 63;
    int row = (i >> 6) % 56;
    int chunk = ((i >> 6) / 56) % (CI / 8);
    int cb = (i >> 6) / 56 / (CI / 8);
    int ci = chunk * 8 + row / 7;
    int t = row % 7;
    int c_lo = (p < 32) ? p : p + 32;
    int co_lo = cb * 128 + c_lo;
    wp[i] = make_float2(w[((size_t)co_lo * CI + ci) * 7 + t],
                        w[((size_t)(co_lo + 32) * CI + ci) * 7 + t]);
}

// ==================== conv1: Cin=1, tile 64 l x 128 c ====================
__global__ __launch_bounds__(256) void conv1_fast_kernel(const float* __restrict__ x,
                                                         const float* __restrict__ w,
                                                         const float* __restrict__ bias) {
    __shared__ float a_s[136];
    int tid = threadIdx.x;
    int lane = tid & 31, lg = tid >> 5;
    int l0 = blockIdx.x * 64;
    int b = blockIdx.y;

    for (int p = tid; p < 133; p += 256) {
        int pg = 2 * l0 - 3 + p;
        a_s[p] = (pg >= 0 && pg < SLEN) ? x[(size_t)b * SLEN + pg] : 0.f;
    }
    __syncthreads();

    float wr[4][7], bv[4];
#pragma unroll
    for (int c = 0; c < 4; c++) {
        int ch = lane + 32 * c;
        bv[c] = bias[ch];
#pragma unroll
        for (int t = 0; t < 7; t++) wr[c][t] = w[ch * 7 + t];
    }

    float xv[21];
#pragma unroll
    for (int p = 0; p < 21; p++) xv[p] = a_s[16 * lg + p];

    float acc[4][8];
#pragma unroll
    for (int c = 0; c < 4; c++)
#pragma unroll
        for (int j = 0; j < 8; j++) acc[c][j] = bv[c];
#pragma unroll
    for (int t = 0; t < 7; t++) {
#pragma unroll
        for (int j = 0; j < 8; j++) {
            float xx = xv[2 * j + t];
#pragma unroll
            for (int c = 0; c < 4; c++)
                acc[c][j] = fmaf(wr[c][t], xx, acc[c][j]);
        }
    }
#pragma unroll
    for (int c = 0; c < 4; c++) {
        int ch = lane + 32 * c;
#pragma unroll
        for (int j = 0; j < 8; j++) {
            int l = l0 + lg * 8 + j;
            g_conv1[((size_t)b * C1 + ch) * L1LEN + l] = fmaxf(acc[c][j], 0.f);
        }
    }
}

// ==================== conv2/3: FFMA2 + cp.async double-buffered staging ====================
// Per buffer: input 8 rows x 168 floats (aligned window [2l0-16, 2l0+144)), then
// weights 56 rows x 64 float2 (pre-packed pairs). BUFSZ = 5376 + 28672 = 34048.
#define CV_INSTRIDE 168
#define CV_INSZ (8 * CV_INSTRIDE * 4)       // 5376
#define CV_WSZ  (56 * 64 * 8)               // 28672
#define CV_BUFSZ (CV_INSZ + CV_WSZ)         // 34048
#define CV_SMEM  (2 * CV_BUFSZ)             // 68096

template <int CI, int CO, int LOUT, bool RELU, bool TRANS_OUT, int STAGE>
__global__ __launch_bounds__(256, 3) void conv_fast_kernel(const float* __restrict__ bias) {
    const float*  in = (STAGE == 2) ? g_conv1 : g_conv2;
    const float2* wp = (STAGE == 2) ? g_w2p : g_w3p;
    float*       out = (STAGE == 2) ? g_conv2 : g_feats;

    const int LIN = 2 * LOUT;
    const int NCH = CI / 8;
    extern __shared__ __align__(16) char dsm[];
    uint32_t sb = smem_u32(dsm);

    int tid = threadIdx.x;
    int lane = tid & 31, lg = tid >> 5;
    int l0  = blockIdx.x * 64;
    int cb  = blockIdx.y;               // co0 = cb*128
    int b   = blockIdx.z;

    const int gs = 2 * l0 - 16;         // aligned window start (multiple of 16 floats)

    auto stage_chunk = [&](int kc, int s) {
        uint32_t base = sb + s * CV_BUFSZ;
        // input: 8 ci x 40 chunks of 16B
#pragma unroll
        for (int r = 0; r < 2; r++) {
            int i = tid + r * 256;
            if (i < 320) {
                int ci = i / 40, q = i % 40;
                int gf = gs + q * 4;
                int valid = (gf >= 0 && gf + 4 <= LIN) ? 16 : 0;
                const float* src = in + ((size_t)b * CI + kc * 8 + ci) * LIN + (gf < 0 ? 0 : gf);
                cp_async16z(base + ci * (CV_INSTRIDE * 4) + q * 16, src, valid);
            }
        }
        // weights: 1792 chunks of 16B (2 float2 each), fully contiguous
        const char* wsrc = (const char*)(wp + ((size_t)cb * NCH + kc) * 3584);
        uint32_t wdst = base + CV_INSZ;
#pragma unroll
        for (int r = 0; r < 7; r++) {
            int i = tid + r * 256;
            cp_async16(wdst + i * 16, wsrc + i * 16);
        }
        CP_COMMIT();
    };

    uint64_t acc2[2][8];
#pragma unroll
    for (int cp = 0; cp < 2; cp++)
#pragma unroll
        for (int j = 0; j < 8; j++) acc2[cp][j] = 0ull;

    stage_chunk(0, 0);

    for (int kc = 0; kc < NCH; kc++) {
        CP_WAIT0();
        __syncthreads();
        if (kc + 1 < NCH) stage_chunk(kc + 1, (kc + 1) & 1);

        const float*  in_s = (const float*)(dsm + (kc & 1) * CV_BUFSZ);
        const float2* w_s  = (const float2*)(dsm + (kc & 1) * CV_BUFSZ + CV_INSZ);

#pragma unroll
        for (int ci = 0; ci < 8; ci++) {
            const float* inrow = in_s + ci * CV_INSTRIDE + 13 + 16 * lg;
            float xvf[21];
#pragma unroll
            for (int p = 0; p < 21; p++) xvf[p] = inrow[p];

#pragma unroll
            for (int t = 0; t < 7; t++) {
                const float2* wrow = w_s + (ci * 7 + t) * 64;
                float2 w0f = wrow[lane];
                float2 w1f = wrow[32 + lane];
                uint64_t w0, w1;
                memcpy(&w0, &w0f, 8);
                memcpy(&w1, &w1f, 8);
#pragma unroll
                for (int j = 0; j < 8; j++) {
                    uint64_t xd = pkdup(xvf[2 * j + t]);
                    fma2(acc2[0][j], w0, xd);
                    fma2(acc2[1][j], w1, xd);
                }
            }
        }
        __syncthreads();
    }

#pragma unroll
    for (int cp = 0; cp < 2; cp++) {
#pragma unroll
        for (int half = 0; half < 2; half++) {
            int c = cp * 2 + half;
            int co = cb * 128 + lane + 32 * c;
            float bv = bias[co];
#pragma unroll
            for (int j = 0; j < 8; j++) {
                float2 a = upk(acc2[cp][j]);
                float r = (half == 0 ? a.x : a.y) + bv;
                if (RELU) r = fmaxf(r, 0.f);
                int l = l0 + lg * 8 + j;
                if (TRANS_OUT) {
                    size_t idx = ((size_t)b * LOUT + l) * CO + co;
                    out[idx] = r;
                    g_fhi[idx] = __float2bfloat16_rn(r);   // fused feats split
                } else {
                    out[((size_t)b * CO + co) * LOUT + l] = r;
                }
            }
        }
    }
}

// ==================== bf16 conversion (codebook) ====================
__global__ void split_cb_kernel(const float* __restrict__ cb) {
    int i = blockIdx.x * blockDim.x + threadIdx.x;
    if (i >= KCB * VOCAB * HID) return;
    g_chi[i] = __float2bfloat16_rn(cb[i]);
}

// ==================== c2 + per-codebook max norm ====================
__global__ void c2_kernel(const float* __restrict__ cb) {
    int row = blockIdx.x * 8 + (threadIdx.x >> 5);
    int lane = threadIdx.x & 31;
    const float* p = cb + (size_t)row * HID;
    float s = 0.f;
#pragma unroll 4
    for (int h = lane; h < HID; h += 32) {
        float v = p[h];
        s = fmaf(v, v, s);
    }
#pragma unroll
    for (int off = 16; off; off >>= 1)
        s += __shfl_xor_sync(0xffffffffu, s, off);
    if (lane == 0) g_c2[row] = s;
}

__global__ void cbmax_kernel() {
    __shared__ float red[256];
    int k = blockIdx.x;
    float m = 0.f;
    for (int v = threadIdx.x; v < VOCAB; v += 256)
        m = fmaxf(m, g_c2[k * VOCAB + v]);
    red[threadIdx.x] = m;
    __syncthreads();
    for (int s = 128; s; s >>= 1) {
        if (threadIdx.x < s) red[threadIdx.x] = fmaxf(red[threadIdx.x], red[threadIdx.x + s]);
        __syncthreads();
    }
    if (threadIdx.x == 0) g_cbmax[k] = sqrtf(red[0]);
}

// ==================== stage 1: pure bf16 hi GEMM -> fp16 cross ====================
#define ST_A 0
#define ST_B 18432
#define ST_STRIDE 55296        // A(128x144) + B(256x144)
#define ST_TOTAL 110592

__device__ __forceinline__ void mma_bf16(float* c, const uint32_t* a, const uint32_t* b0, const uint32_t* b1) {
    asm volatile(
        "mma.sync.aligned.m16n8k16.row.col.f32.bf16.bf16.f32 "
        "{%0,%1,%2,%3}, {%4,%5,%6,%7}, {%8,%9}, {%0,%1,%2,%3};"
        : "+f"(c[0]), "+f"(c[1]), "+f"(c[2]), "+f"(c[3])
        : "r"(a[0]), "r"(a[1]), "r"(a[2]), "r"(a[3]), "r"(*b0), "r"(*b1));
}
__device__ __forceinline__ void ldsm_x4(uint32_t* r, uint32_t addr) {
    asm volatile("ldmatrix.sync.aligned.m8n8.x4.shared.b16 {%0,%1,%2,%3}, [%4];"
                 : "=r"(r[0]), "=r"(r[1]), "=r"(r[2]), "=r"(r[3]) : "r"(addr));
}

__global__ __launch_bounds__(256, 1) void gemm_hi_kernel() {
    extern __shared__ char smem[];
    uint32_t sbase = smem_u32(smem);

    const int tid = threadIdx.x;
    const int wid = tid >> 5, lane = tid & 31;
    const int wm = wid >> 2, wn = wid & 3;
    const int g = lane >> 2, t = lane & 3;
    const int lt = blockIdx.x;
    const int vt = blockIdx.y;
    const int bk = blockIdx.z;
    const int b = bk >> 2, k = bk & 3;

    const __nv_bfloat16* A  = g_fhi + ((size_t)b * L3LEN + lt * 128) * HID;
    const __nv_bfloat16* Bm = g_chi + ((size_t)k * VOCAB + vt * 256) * HID;

    auto load_chunk = [&](int kc, int s) {
        uint32_t st = sbase + s * ST_STRIDE;
#pragma unroll
        for (int j = 0; j < 12; j++) {
            int idx = tid + j * 256;
            if (idx < 1024) {
                int r = idx >> 3, q = idx & 7;
                cp_async16(st + ST_A + r * 144 + q * 16,
                           A + (size_t)r * HID + kc * 64 + q * 8);
            } else {
                int i2 = idx - 1024;
                int r = i2 >> 3, q = i2 & 7;
                cp_async16(st + ST_B + r * 144 + q * 16,
                           Bm + (size_t)r * HID + kc * 64 + q * 8);
            }
        }
        CP_COMMIT();
    };

    int lrow = (lane & 7) + ((lane >> 3) & 1) * 8;
    int lcol = (lane >> 4) * 16;
    uint32_t a_ad[2][4], b_ad[2][4];
#pragma unroll
    for (int s = 0; s < 2; s++) {
#pragma unroll
        for (int mi = 0; mi < 4; mi++)
            a_ad[s][mi] = sbase + s * ST_STRIDE + ST_A +
                          (wm * 64 + mi * 16 + lrow) * 144 + lcol;
#pragma unroll
        for (int j = 0; j < 4; j++)
            b_ad[s][j] = sbase + s * ST_STRIDE + ST_B +
                         (wn * 64 + j * 16 + lrow) * 144 + lcol;
    }

    float acc[4][8][4];
#pragma unroll
    for (int mi = 0; mi < 4; mi++)
#pragma unroll
        for (int ni = 0; ni < 8; ni++)
#pragma unroll
            for (int j = 0; j < 4; j++) acc[mi][ni][j] = 0.f;

    load_chunk(0, 0);
    for (int kc = 0; kc < 8; kc++) {
        if (kc < 7) {
            load_chunk(kc + 1, (kc + 1) & 1);
            asm volatile("cp.async.wait_group 1;" ::: "memory");
        } else {
            CP_WAIT0();
        }
        __syncthreads();
        int st = kc & 1;
#pragma unroll
        for (int ks = 0; ks < 4; ks++) {
            uint32_t af[4][4], bfv[4][4];
#pragma unroll
            for (int mi = 0; mi < 4; mi++) ldsm_x4(af[mi], a_ad[st][mi] + ks * 32);
#pragma unroll
            for (int j = 0; j < 4; j++)  ldsm_x4(bfv[j], b_ad[st][j] + ks * 32);
#pragma unroll
            for (int j = 0; j < 4; j++) {
#pragma unroll
                for (int mi = 0; mi < 4; mi++) {
                    mma_bf16(acc[mi][2 * j],     af[mi], &bfv[j][0], &bfv[j][2]);
                    mma_bf16(acc[mi][2 * j + 1], af[mi], &bfv[j][1], &bfv[j][3]);
                }
            }
        }
        __syncthreads();
    }

#pragma unroll
    for (int mi = 0; mi < 4; mi++) {
        int row = lt * 128 + wm * 64 + mi * 16 + g;
        size_t code = (size_t)(b * KCB + k) * L3LEN + row;
        __half* out0 = g_cross + code * VOCAB;
        __half* out1 = g_cross + (code + 8) * VOCAB;
#pragma unroll
        for (int ni = 0; ni < 8; ni++) {
            int col = vt * 256 + wn * 64 + ni * 8 + 2 * t;
            *(__half2*)(out0 + col) = __floats2half2_rn(acc[mi][ni][0], acc[mi][ni][1]);
            *(__half2*)(out1 + col) = __floats2half2_rn(acc[mi][ni][2], acc[mi][ni][3]);
        }
    }
}

// ==================== stage 2: per-token select + bounded exact rescore ====================
__device__ __forceinline__ void upd_min(float& m, float& m2, int& idx, float d, int v) {
    if (d < m)       { m2 = m; m = d; idx = v; }
    else if (d < m2) { m2 = d; }
}
__device__ __forceinline__ void merge_min(float& m, float& m2, int& idx,
                                          float om, float om2, int oidx) {
    if (om < m) { m2 = fminf(m, om2); m = om; idx = oidx; }
    else        { m2 = fminf(m2, om); }
}

__global__ __launch_bounds__(256) void select_kernel(const float* __restrict__ cb) {
    __shared__ float c2_s[VOCAB];
    int tid = threadIdx.x;
    int wid = tid >> 5, lane = tid & 31;
    int code0 = blockIdx.x * 8;
    int k = (code0 >> 12) & (KCB - 1);

    for (int i = tid; i < VOCAB; i += 256)
        c2_s[i] = g_c2[k * VOCAB + i];
    __syncthreads();

    int code = code0 + wid;
    int l = code & (L3LEN - 1);
    int b = code >> 14;
    const __half2* crow2 = (const __half2*)(g_cross + (size_t)code * VOCAB);

    float minv = CUDART_INF_F, min2 = CUDART_INF_F;
    int mini = 0;
#pragma unroll 4
    for (int i = 0; i < 32; i++) {
        __half2 h = crow2[i * 32 + lane];
        int v = i * 64 + lane * 2;
        float d0 = c2_s[v]     - 2.f * __low2float(h);
        float d1 = c2_s[v + 1] - 2.f * __high2float(h);
        upd_min(minv, min2, mini, d0, v);
        upd_min(minv, min2, mini, d1, v + 1);
    }
#pragma unroll
    for (int off = 16; off; off >>= 1) {
        float om  = __shfl_xor_sync(0xffffffffu, minv, off);
        float om2 = __shfl_xor_sync(0xffffffffu, min2, off);
        int   oi  = __shfl_xor_sync(0xffffffffu, mini, off);
        merge_min(minv, min2, mini, om, om2, oi);
    }

    const float* f = g_feats + ((size_t)b * L3LEN + l) * HID;
    float fr[16];
    float n2 = 0.f;
#pragma unroll
    for (int j = 0; j < 16; j++) {
        fr[j] = f[j * 32 + lane];
        n2 = fmaf(fr[j], fr[j], n2);
    }
#pragma unroll
    for (int off = 16; off; off >>= 1)
        n2 += __shfl_xor_sync(0xffffffffu, n2, off);

    float TH = 0.009f * sqrtf(n2) * g_cbmax[k] + 1.0f;

    if (min2 - minv > TH) {
        if (lane == 0) g_tokens[code] = mini;
        return;
    }

    float thr = minv + TH;
    float bestd = CUDART_INF_F;
    int besti = VOCAB;
    for (int i = 0; i < 32; i++) {
        __half2 h = crow2[i * 32 + lane];
        int v = i * 64 + lane * 2;
        float d0 = c2_s[v]     - 2.f * __low2float(h);
        float d1 = c2_s[v + 1] - 2.f * __high2float(h);
        unsigned m0 = __ballot_sync(0xffffffffu, d0 <= thr);
        unsigned m1 = __ballot_sync(0xffffffffu, d1 <= thr);
        while (m0 | m1) {
            int s0 = m0 ? (__ffs(m0) - 1) : 33;
            int s1 = m1 ? (__ffs(m1) - 1) : 33;
            int vc;
            if (s0 <= s1) { vc = i * 64 + s0 * 2;     m0 &= m0 - 1; }
            else          { vc = i * 64 + s1 * 2 + 1; m1 &= m1 - 1; }
            const float* c = cb + ((size_t)k * VOCAB + vc) * HID;
            float dot = 0.f;
#pragma unroll
            for (int j = 0; j < 16; j++)
                dot = fmaf(fr[j], c[j * 32 + lane], dot);
#pragma unroll
            for (int off = 16; off; off >>= 1)
                dot += __shfl_xor_sync(0xffffffffu, dot, off);
            float de = c2_s[vc] - 2.f * dot;
            if (de < bestd || (de == bestd && vc < besti)) { bestd = de; besti = vc; }
        }
    }
    if (lane == 0) g_tokens[code] = besti;
}

// ==================== outputs ====================
__global__ void emb_kernel(const float* __restrict__ embedding, float* __restrict__ out) {
    int bl = blockIdx.x;
    int b = bl >> 12;
    int l = bl & (L3LEN - 1);
    int t0 = g_tokens[((size_t)b * KCB + 0) * L3LEN + l];
    int t1 = g_tokens[((size_t)b * KCB + 1) * L3LEN + l];
    int t2 = g_tokens[((size_t)b * KCB + 2) * L3LEN + l];
    int t3 = g_tokens[((size_t)b * KCB + 3) * L3LEN + l];
    const float4* e0 = (const float4*)(embedding + (size_t)t0 * HID);
    const float4* e1 = (const float4*)(embedding + (size_t)t1 * HID);
    const float4* e2 = (const float4*)(embedding + (size_t)t2 * HID);
    const float4* e3 = (const float4*)(embedding + (size_t)t3 * HID);
    int h = threadIdx.x;
    float4 v0 = e0[h], v1 = e1[h], v2 = e2[h], v3 = e3[h];
    float4 rr;
    rr.x = 0.25f * (v0.x + v1.x + v2.x + v3.x);
    rr.y = 0.25f * (v0.y + v1.y + v2.y + v3.y);
    rr.z = 0.25f * (v0.z + v1.z + v2.z + v3.z);
    rr.w = 0.25f * (v0.w + v1.w + v2.w + v3.w);
    ((float4*)(out + ((size_t)b * L3LEN + l) * HID))[h] = rr;
}

__global__ void tok2f_kernel(float* __restrict__ out) {
    int i = blockIdx.x * blockDim.x + threadIdx.x;
    if (i < NTOK) out[i] = (float)g_tokens[i];
}

// ==================== launch ====================
extern "C" void kernel_launch(void* const* d_in, const int* in_sizes, int n_in,
                              void* d_out, int out_size) {
    const float* audio = 0; const float* w1 = 0; const float* b1 = 0;
    const float* w2 = 0; const float* b2 = 0; const float* w3 = 0; const float* b3 = 0;
    const float* codebook = 0; const float* embedding = 0;
    for (int i = 0; i < n_in; i++) {
        const float* p = (const float*)d_in[i];
        switch (in_sizes[i]) {
            case BATCH * SLEN:      audio = p; break;
            case C1 * 1 * 7:        w1 = p; break;
            case C1:                b1 = p; break;
            case C2 * C1 * 7:       w2 = p; break;
            case C2:                b2 = p; break;
            case HID * C2 * 7:      w3 = p; break;
            case HID:               b3 = p; break;
            case KCB * VOCAB * HID: codebook = p; break;
            case VOCAB * HID:       embedding = p; break;
            default: break;
        }
    }

    cudaFuncSetAttribute(gemm_hi_kernel,
                         cudaFuncAttributeMaxDynamicSharedMemorySize, ST_TOTAL);
    cudaFuncSetAttribute(conv_fast_kernel<C1, C2, L2LEN, true, false, 2>,
                         cudaFuncAttributeMaxDynamicSharedMemorySize, CV_SMEM);
    cudaFuncSetAttribute(conv_fast_kernel<C2, HID, L3LEN, false, true, 3>,
                         cudaFuncAttributeMaxDynamicSharedMemorySize, CV_SMEM);

    // order chosen so the 4th launch (ncu capture slot) = conv_fast<stage2>
    {
        dim3 grid(L1LEN / 64, BATCH);
        conv1_fast_kernel<<<grid, 256>>>(audio, w1, b1);
    }
    wpack_kernel<C1, C2, 2><<<((C2 / 128) * (C1 / 8) * 3584 + 255) / 256, 256>>>(w2);
    wpack_kernel<C2, HID, 3><<<((HID / 128) * (C2 / 8) * 3584 + 255) / 256, 256>>>(w3);
    {
        dim3 grid(L2LEN / 64, C2 / 128, BATCH);
        conv_fast_kernel<C1, C2, L2LEN, true, false, 2><<<grid, 256, CV_SMEM>>>(b2);
    }
    {
        dim3 grid(L3LEN / 64, HID / 128, BATCH);
        conv_fast_kernel<C2, HID, L3LEN, false, true, 3><<<grid, 256, CV_SMEM>>>(b3);
    }
    split_cb_kernel<<<(KCB * VOCAB * HID) / 256, 256>>>(codebook);
    c2_kernel<<<(KCB * VOCAB) / 8, 256>>>(codebook);
    cbmax_kernel<<<KCB, 256>>>();

    {
        dim3 grid(L3LEN / 128, VOCAB / 256, KCB * BATCH);
        gemm_hi_kernel<<<grid, 256, ST_TOTAL>>>();
    }
    select_kernel<<<NTOK / 8, 256>>>(codebook);

    const int TOK = NTOK;
    const int EMB = BATCH * L3LEN * HID;
    float* out = (float*)d_out;
    if (out_size >= TOK + EMB) {
        tok2f_kernel<<<(TOK + 255) / 256, 256>>>(out);
        emb_kernel<<<BATCH * L3LEN, 128>>>(embedding, out + TOK);
    } else if (out_size >= EMB) {
        emb_kernel<<<BATCH * L3LEN, 128>>>(embedding, out);
    } else {
        tok2f_kernel<<<(TOK + 255) / 256, 256>>>(out);
    }
}